// round 13
// baseline (speedup 1.0000x reference)
#include <cuda_runtime.h>
#include <cuda_bf16.h>
#include <cuda_fp16.h>
#include <math.h>

// ---------------------------------------------------------------------------
// Problem constants
// ---------------------------------------------------------------------------
#define NN   50000
#define FIN  256
#define HH   128
#define CC   64
#define EMAX 1600000
#define NBLK 196              // ceil(NN/256)

// ---------------------------------------------------------------------------
// Static scratch
// ---------------------------------------------------------------------------
constexpr long long OFF_XL1 = 0;
constexpr long long OFF_XR1 = (long long)NN * HH;
constexpr long long OFF_XL2 = 2LL * NN * HH;
constexpr long long OFF_XR2 = OFF_XL2 + (long long)NN * CC;
constexpr long long POOL_SZ = OFF_XR2 + (long long)NN * CC;

__device__ float g_pool[POOL_SZ];

__device__ __nv_bfloat16 g_xhi[(long long)NN * FIN];
__device__ __nv_bfloat16 g_xlo[(long long)NN * FIN];
__device__ __nv_bfloat16 g_hhi[(long long)NN * HH];
__device__ __nv_bfloat16 g_hlo[(long long)NN * HH];
// packed weights: W1L @0 (32768), W1R @32768, W2L @65536 (8192), W2R @73728
__device__ __nv_bfloat16 g_whi[81920];
__device__ __nv_bfloat16 g_wlo[81920];

// fp16 gather operands for node kernels (xl transforms)
__device__ __half g_xl1h[(long long)NN * HH];
__device__ __half g_xl2h[(long long)NN * CC];

__device__ float g_dl[NN];
__device__ float g_dr[NN];

__device__ int g_cnt[NN];
__device__ int g_off[NN + 1];
__device__ int g_cur[NN];
__device__ int g_bsum[256];
__device__ int g_ssrc[EMAX];

// ---------------------------------------------------------------------------
// fp32 -> bf16 hi/lo conversion
// ---------------------------------------------------------------------------
__global__ void cvt_kernel(const float* __restrict__ src, int sel,
                           long long doff, long long n) {
    __nv_bfloat16* hi = sel ? g_whi : g_xhi;
    __nv_bfloat16* lo = sel ? g_wlo : g_xlo;
    long long i = ((long long)blockIdx.x * blockDim.x + threadIdx.x) * 4;
    if (i >= n) return;
    float4 v = *(const float4*)(src + i);
    float vv[4] = {v.x, v.y, v.z, v.w};
    __nv_bfloat16 h[4], l[4];
    #pragma unroll
    for (int j = 0; j < 4; j++) {
        h[j] = __float2bfloat16(vv[j]);
        l[j] = __float2bfloat16(vv[j] - __bfloat162float(h[j]));
    }
    *(__nv_bfloat162*)(hi + doff + i)     = __nv_bfloat162(h[0], h[1]);
    *(__nv_bfloat162*)(hi + doff + i + 2) = __nv_bfloat162(h[2], h[3]);
    *(__nv_bfloat162*)(lo + doff + i)     = __nv_bfloat162(l[0], l[1]);
    *(__nv_bfloat162*)(lo + doff + i + 2) = __nv_bfloat162(l[2], l[3]);
}

// ---------------------------------------------------------------------------
// CSR construction
// ---------------------------------------------------------------------------
__global__ void zero_cnt_kernel() {
    int i = blockIdx.x * blockDim.x + threadIdx.x;
    if (i < NN) g_cnt[i] = 0;
}

__global__ void hist_kernel(const int* __restrict__ dst, int E) {
    int i0 = (blockIdx.x * blockDim.x + threadIdx.x) * 4;
    #pragma unroll
    for (int j = 0; j < 4; j++) {
        int i = i0 + j;
        if (i < E) atomicAdd(&g_cnt[dst[i]], 1);
    }
}

__global__ void scan1_kernel() {
    __shared__ int wt[8];
    int t = threadIdx.x, lane = t & 31, wid = t >> 5;
    int idx = blockIdx.x * 256 + t;
    int v = (idx < NN) ? g_cnt[idx] : 0;
    int x = v;
    #pragma unroll
    for (int o = 1; o < 32; o <<= 1) {
        int tmp = __shfl_up_sync(0xFFFFFFFFu, x, o);
        if (lane >= o) x += tmp;
    }
    if (lane == 31) wt[wid] = x;
    __syncthreads();
    if (wid == 0 && lane < 8) {
        int w = wt[lane], wx = w;
        #pragma unroll
        for (int o = 1; o < 8; o <<= 1) {
            int tmp = __shfl_up_sync(0xFFu, wx, o);
            if (lane >= o) wx += tmp;
        }
        wt[lane] = wx - w;
    }
    __syncthreads();
    int excl = x - v + wt[wid];
    if (idx < NN) g_off[idx] = excl;
    if (t == 255) g_bsum[blockIdx.x] = excl + v;
}

__global__ void scan2_kernel() {
    __shared__ int wt[8];
    int t = threadIdx.x, lane = t & 31, wid = t >> 5;
    int v = (t < NBLK) ? g_bsum[t] : 0;
    int x = v;
    #pragma unroll
    for (int o = 1; o < 32; o <<= 1) {
        int tmp = __shfl_up_sync(0xFFFFFFFFu, x, o);
        if (lane >= o) x += tmp;
    }
    if (lane == 31) wt[wid] = x;
    __syncthreads();
    if (wid == 0 && lane < 8) {
        int w = wt[lane], wx = w;
        #pragma unroll
        for (int o = 1; o < 8; o <<= 1) {
            int tmp = __shfl_up_sync(0xFFu, wx, o);
            if (lane >= o) wx += tmp;
        }
        wt[lane] = wx - w;
    }
    __syncthreads();
    if (t < NBLK) g_bsum[t] = x - v + wt[wid];
}

__global__ void scan3_kernel(int E) {
    int idx = blockIdx.x * 256 + threadIdx.x;
    if (idx < NN) {
        int o = g_off[idx] + g_bsum[blockIdx.x];
        g_off[idx] = o;
        g_cur[idx] = o;
    }
    if (idx == 0) g_off[NN] = E;
}

__global__ void scatter_kernel(const int* __restrict__ src,
                               const int* __restrict__ dst, int E) {
    int i0 = (blockIdx.x * blockDim.x + threadIdx.x) * 4;
    #pragma unroll
    for (int j = 0; j < 4; j++) {
        int i = i0 + j;
        if (i < E) {
            int pos = atomicAdd(&g_cur[dst[i]], 1);
            g_ssrc[pos] = src[i];
        }
    }
}

// ---------------------------------------------------------------------------
// Tensor-core GEMM, bf16 hi/lo, 3-stage cp.async pipeline, merged L/R via
// blockIdx.y, fused att-dot epilogue (-> g_dl y=0, g_dr y=1).
// y==0 (L operand) emits fp16 xl instead of fp32 C.
// ---------------------------------------------------------------------------
__device__ __forceinline__ void ldsm_x4(unsigned* r, unsigned addr) {
    asm volatile("ldmatrix.sync.aligned.m8n8.x4.shared.b16 {%0,%1,%2,%3}, [%4];"
                 : "=r"(r[0]), "=r"(r[1]), "=r"(r[2]), "=r"(r[3]) : "r"(addr));
}
__device__ __forceinline__ void ldsm_x4t(unsigned* r, unsigned addr) {
    asm volatile("ldmatrix.sync.aligned.m8n8.x4.trans.shared.b16 {%0,%1,%2,%3}, [%4];"
                 : "=r"(r[0]), "=r"(r[1]), "=r"(r[2]), "=r"(r[3]) : "r"(addr));
}
__device__ __forceinline__ void mma_bf16(float* c, const unsigned* a, const unsigned* b) {
    asm volatile(
        "mma.sync.aligned.m16n8k16.row.col.f32.bf16.bf16.f32 "
        "{%0,%1,%2,%3}, {%4,%5,%6,%7}, {%8,%9}, {%0,%1,%2,%3};"
        : "+f"(c[0]), "+f"(c[1]), "+f"(c[2]), "+f"(c[3])
        : "r"(a[0]), "r"(a[1]), "r"(a[2]), "r"(a[3]), "r"(b[0]), "r"(b[1]));
}
__device__ __forceinline__ void cp16(unsigned dst, const void* src, bool valid) {
    int sz = valid ? 16 : 0;
    asm volatile("cp.async.cg.shared.global [%0], [%1], 16, %2;"
                 :: "r"(dst), "l"(src), "r"(sz));
}
#define CP_COMMIT() asm volatile("cp.async.commit_group;")
#define CP_WAIT1()  asm volatile("cp.async.wait_group 1;")
#define CP_WAIT0()  asm volatile("cp.async.wait_group 0;")

template<int TN>
__global__ __launch_bounds__(256)
void gemm_tc_kernel(int a_sel, int K, long long w_off0, long long w_stride,
                    long long c_off0, long long c_stride, int Fout,
                    const float* __restrict__ att) {
    constexpr int TM = 128, BK = 16;
    constexpr int APITCH = 24;
    constexpr int BPITCH = TN + 8;
    constexpr int NF = TN / 32;
    constexpr int ASTAGE = TM * APITCH;
    constexpr int BSTAGE = BK * BPITCH;

    const __nv_bfloat16* Ahi = a_sel ? g_hhi : g_xhi;
    const __nv_bfloat16* Alo = a_sel ? g_hlo : g_xlo;
    long long w_off = w_off0 + (long long)blockIdx.y * w_stride;
    const __nv_bfloat16* Whi = g_whi + w_off;
    const __nv_bfloat16* Wlo = g_wlo + w_off;
    float* C = g_pool + c_off0 + (long long)blockIdx.y * c_stride;
    float* dots = blockIdx.y ? g_dr : g_dl;
    bool isL = (blockIdx.y == 0);
    __half* xh = a_sel ? g_xl2h : g_xl1h;

    extern __shared__ __align__(16) __nv_bfloat16 sm[];
    __nv_bfloat16* Ah = sm;
    __nv_bfloat16* Al = Ah + 3 * ASTAGE;
    __nv_bfloat16* Bh = Al + 3 * ASTAGE;
    __nv_bfloat16* Bl = Bh + 3 * BSTAGE;
    float* sdot = (float*)sm;          // reused after mainloop

    int t = threadIdx.x;
    int lane = t & 31, wid = t >> 5;
    int warp_m = wid & 1, warp_n = wid >> 1;
    int m_off = warp_m * 64, n_off = warp_n * (TN / 4);
    int row0 = blockIdx.x * TM;
    int N = NN;

    float c[4][NF][4];
    #pragma unroll
    for (int i = 0; i < 4; i++)
        #pragma unroll
        for (int j = 0; j < NF; j++)
            #pragma unroll
            for (int q = 0; q < 4; q++) c[i][j][q] = 0.0f;

    int g = lane >> 3, r = lane & 7;
    int a_row = (g & 1) * 8 + r;
    int a_col = (g >> 1) * 8;
    int b_krow = lane & 15;
    int b_chalf = (lane >> 4) * 8;

    int am = t >> 1;
    int ac = (t & 1) * 8;

    const int NIT = K / BK;

    auto load_stage = [&](int it, int s) {
        int k0 = it * BK;
        int grow = row0 + am;
        bool v = grow < N;
        cp16((unsigned)__cvta_generic_to_shared(Ah + s * ASTAGE + am * APITCH + ac),
             Ahi + (size_t)grow * K + k0 + ac, v);
        cp16((unsigned)__cvta_generic_to_shared(Al + s * ASTAGE + am * APITCH + ac),
             Alo + (size_t)grow * K + k0 + ac, v);
        if (TN == 128) {
            int kk = t >> 4, ch = (t & 15) * 8;
            cp16((unsigned)__cvta_generic_to_shared(Bh + s * BSTAGE + kk * BPITCH + ch),
                 Whi + (size_t)(k0 + kk) * Fout + ch, true);
            cp16((unsigned)__cvta_generic_to_shared(Bl + s * BSTAGE + kk * BPITCH + ch),
                 Wlo + (size_t)(k0 + kk) * Fout + ch, true);
        } else {
            if (t < 128) {
                int kk = t >> 3, ch = (t & 7) * 8;
                cp16((unsigned)__cvta_generic_to_shared(Bh + s * BSTAGE + kk * BPITCH + ch),
                     Whi + (size_t)(k0 + kk) * Fout + ch, true);
                cp16((unsigned)__cvta_generic_to_shared(Bl + s * BSTAGE + kk * BPITCH + ch),
                     Wlo + (size_t)(k0 + kk) * Fout + ch, true);
            }
        }
    };

    load_stage(0, 0);
    CP_COMMIT();
    if (NIT > 1) load_stage(1, 1);
    CP_COMMIT();

    for (int it = 0; it < NIT; it++) {
        CP_WAIT1();
        __syncthreads();
        if (it + 2 < NIT) load_stage(it + 2, (it + 2) % 3);
        CP_COMMIT();

        int s = it % 3;
        unsigned ah[4][4], bh[NF][2];
        #pragma unroll
        for (int i = 0; i < 4; i++)
            ldsm_x4(ah[i], (unsigned)__cvta_generic_to_shared(
                        Ah + s * ASTAGE + (m_off + i * 16 + a_row) * APITCH + a_col));
        #pragma unroll
        for (int j = 0; j < NF; j += 2)
            ldsm_x4t(&bh[j][0], (unsigned)__cvta_generic_to_shared(
                        Bh + s * BSTAGE + b_krow * BPITCH + n_off + j * 8 + b_chalf));
        #pragma unroll
        for (int i = 0; i < 4; i++)
            #pragma unroll
            for (int j = 0; j < NF; j++) mma_bf16(c[i][j], ah[i], bh[j]);

        unsigned bl[NF][2];
        #pragma unroll
        for (int j = 0; j < NF; j += 2)
            ldsm_x4t(&bl[j][0], (unsigned)__cvta_generic_to_shared(
                        Bl + s * BSTAGE + b_krow * BPITCH + n_off + j * 8 + b_chalf));
        #pragma unroll
        for (int i = 0; i < 4; i++)
            #pragma unroll
            for (int j = 0; j < NF; j++) mma_bf16(c[i][j], ah[i], bl[j]);

        unsigned al[4][4];
        #pragma unroll
        for (int i = 0; i < 4; i++)
            ldsm_x4(al[i], (unsigned)__cvta_generic_to_shared(
                        Al + s * ASTAGE + (m_off + i * 16 + a_row) * APITCH + a_col));
        #pragma unroll
        for (int i = 0; i < 4; i++)
            #pragma unroll
            for (int j = 0; j < NF; j++) mma_bf16(c[i][j], al[i], bh[j]);
    }

    // ---- epilogue: stores (fp16 xl for L, fp32 for R) + fused att-dot ----
    CP_WAIT0();
    __syncthreads();
    if (t < TM) sdot[t] = 0.0f;
    __syncthreads();

    int lr = lane >> 2;
    int lc = (lane & 3) * 2;
    #pragma unroll
    for (int i = 0; i < 4; i++) {
        int gr = row0 + m_off + i * 16 + lr;
        float p0 = 0.0f, p1 = 0.0f;
        #pragma unroll
        for (int j = 0; j < NF; j++) {
            int gc = n_off + j * 8 + lc;
            float a0 = att[gc], a1 = att[gc + 1];
            if (gr < N) {
                if (isL)
                    *(__half2*)(xh + (size_t)gr * Fout + gc) =
                        __floats2half2_rn(c[i][j][0], c[i][j][1]);
                else
                    *(float2*)(C + (size_t)gr * Fout + gc) =
                        make_float2(c[i][j][0], c[i][j][1]);
            }
            if (gr + 8 < N) {
                if (isL)
                    *(__half2*)(xh + (size_t)(gr + 8) * Fout + gc) =
                        __floats2half2_rn(c[i][j][2], c[i][j][3]);
                else
                    *(float2*)(C + (size_t)(gr + 8) * Fout + gc) =
                        make_float2(c[i][j][2], c[i][j][3]);
            }
            p0 = fmaf(c[i][j][0], a0, fmaf(c[i][j][1], a1, p0));
            p1 = fmaf(c[i][j][2], a0, fmaf(c[i][j][3], a1, p1));
        }
        atomicAdd(&sdot[m_off + i * 16 + lr], p0);
        atomicAdd(&sdot[m_off + i * 16 + lr + 8], p1);
    }
    __syncthreads();
    if (t < TM && row0 + t < N) dots[row0 + t] = sdot[t];
}

// ---------------------------------------------------------------------------
// Fused per-node kernel: warp/node, constant-shift softmax, batched 8-edge
// split-tree reduction, software-pipelined gathers (prefetch next batch's raw
// fp16 rows while reducing the current batch).
// ---------------------------------------------------------------------------
template<int F, bool RELU, bool EMIT_BF16>
__global__ __launch_bounds__(256)
void node_kernel(long long xr_off,
                 const float* __restrict__ att,
                 const float* __restrict__ bias,
                 float* __restrict__ outp) {
    int node = (int)(((long long)blockIdx.x * blockDim.x + threadIdx.x) >> 5);
    int lane = threadIdx.x & 31;
    if (node >= NN) return;

    const __half* xlh = (F == 128) ? g_xl1h : g_xl2h;
    const float* xr = g_pool + xr_off;
    int s0 = g_off[node], s1 = g_off[node + 1];
    float dr = g_dr[node];
    bool h16 = (lane & 16) != 0;
    bool h8  = (lane & 8)  != 0;
    bool h4  = (lane & 4)  != 0;

    if (F == 128) {
        float4 xr4 = *(const float4*)(xr + (size_t)node * F + lane * 4);
        float4 at4 = *(const float4*)(att + lane * 4);
        float4 acc = make_float4(0.f, 0.f, 0.f, 0.f);
        float ssum = 0.0f;

        for (int base = s0; base < s1; base += 32) {
            int cnt = min(32, s1 - base);
            int safe = min(base + lane, s1 - 1);
            int sid = g_ssrc[safe];
            float pinit = 1.5f * (g_dl[sid] + dr);

            // prime: gather batch 0 (raw fp16, 16 regs)
            uint2 raw[8];
            #pragma unroll
            for (int j = 0; j < 8; j++) {
                int sj = __shfl_sync(0xFFFFFFFFu, sid, j);
                raw[j] = *(const uint2*)(xlh + (size_t)sj * F + lane * 4);
            }

            for (int bq = 0; bq < cnt; bq += 8) {
                // prefetch next batch while current reduces
                uint2 rawn[8];
                bool more = (bq + 8 < cnt);
                if (more) {
                    #pragma unroll
                    for (int j = 0; j < 8; j++) {
                        int sj = __shfl_sync(0xFFFFFFFFu, sid, bq + 8 + j);
                        rawn[j] = *(const uint2*)(xlh + (size_t)sj * F + lane * 4);
                    }
                }

                float4 av[8];
                float p[8];
                #pragma unroll
                for (int j = 0; j < 8; j++) {
                    float2 f01 = __half22float2(*(__half2*)&raw[j].x);
                    float2 f23 = __half22float2(*(__half2*)&raw[j].y);
                    av[j] = make_float4(f01.x, f01.y, f23.x, f23.y);
                    float zx = av[j].x + xr4.x, zy = av[j].y + xr4.y;
                    float zz = av[j].z + xr4.z, zw = av[j].w + xr4.w;
                    p[j] = fmaf(at4.x, fabsf(zx),
                           fmaf(at4.y, fabsf(zy),
                           fmaf(at4.z, fabsf(zz), at4.w * fabsf(zw))));
                    if (lane == bq + j) p[j] += pinit;
                }
                // split-tree reduce: 9 shfl for 8 edge sums
                float q[4];
                #pragma unroll
                for (int k = 0; k < 4; k++) {
                    float sendv = h16 ? p[k] : p[k + 4];
                    float recv = __shfl_xor_sync(0xFFFFFFFFu, sendv, 16);
                    q[k] = (h16 ? p[k + 4] : p[k]) + recv;
                }
                float rr[2];
                #pragma unroll
                for (int k = 0; k < 2; k++) {
                    float sendv = h8 ? q[k] : q[k + 2];
                    float recv = __shfl_xor_sync(0xFFFFFFFFu, sendv, 8);
                    rr[k] = (h8 ? q[k + 2] : q[k]) + recv;
                }
                float sendv = h4 ? rr[0] : rr[1];
                float recv = __shfl_xor_sync(0xFFFFFFFFu, sendv, 4);
                float s = (h4 ? rr[1] : rr[0]) + recv;
                s += __shfl_xor_sync(0xFFFFFFFFu, s, 2);
                s += __shfl_xor_sync(0xFFFFFFFFu, s, 1);
                float w = __expf(fmaf(0.4f, s, -20.0f));
                #pragma unroll
                for (int j = 0; j < 8; j++) {
                    float wj = __shfl_sync(0xFFFFFFFFu, w, 4 * j);
                    wj = (bq + j < cnt) ? wj : 0.0f;
                    ssum += wj;
                    acc.x = fmaf(wj, av[j].x, acc.x);
                    acc.y = fmaf(wj, av[j].y, acc.y);
                    acc.z = fmaf(wj, av[j].z, acc.z);
                    acc.w = fmaf(wj, av[j].w, acc.w);
                }
                if (more) {
                    #pragma unroll
                    for (int j = 0; j < 8; j++) raw[j] = rawn[j];
                }
            }
        }
        float inv = 1.0f / (ssum + 1e-16f);
        float4 bb = *(const float4*)(bias + lane * 4);
        float v0 = acc.x * inv + bb.x, v1 = acc.y * inv + bb.y;
        float v2 = acc.z * inv + bb.z, v3 = acc.w * inv + bb.w;
        if (RELU) {
            v0 = fmaxf(v0, 0.f); v1 = fmaxf(v1, 0.f);
            v2 = fmaxf(v2, 0.f); v3 = fmaxf(v3, 0.f);
        }
        if (EMIT_BF16) {
            size_t o = (size_t)node * F + lane * 4;
            __nv_bfloat16 h0 = __float2bfloat16(v0), h1 = __float2bfloat16(v1);
            __nv_bfloat16 h2 = __float2bfloat16(v2), h3 = __float2bfloat16(v3);
            *(__nv_bfloat162*)(g_hhi + o)     = __nv_bfloat162(h0, h1);
            *(__nv_bfloat162*)(g_hhi + o + 2) = __nv_bfloat162(h2, h3);
            *(__nv_bfloat162*)(g_hlo + o) = __nv_bfloat162(
                __float2bfloat16(v0 - __bfloat162float(h0)),
                __float2bfloat16(v1 - __bfloat162float(h1)));
            *(__nv_bfloat162*)(g_hlo + o + 2) = __nv_bfloat162(
                __float2bfloat16(v2 - __bfloat162float(h2)),
                __float2bfloat16(v3 - __bfloat162float(h3)));
        } else {
            *(float4*)(outp + (size_t)node * F + lane * 4) = make_float4(v0, v1, v2, v3);
        }
    } else { // F == 64
        float2 xr2 = *(const float2*)(xr + (size_t)node * F + lane * 2);
        float2 at2 = *(const float2*)(att + lane * 2);
        float2 acc = make_float2(0.f, 0.f);
        float ssum = 0.0f;

        for (int base = s0; base < s1; base += 32) {
            int cnt = min(32, s1 - base);
            int safe = min(base + lane, s1 - 1);
            int sid = g_ssrc[safe];
            float pinit = 1.5f * (g_dl[sid] + dr);

            unsigned raw[8];
            #pragma unroll
            for (int j = 0; j < 8; j++) {
                int sj = __shfl_sync(0xFFFFFFFFu, sid, j);
                raw[j] = *(const unsigned*)(xlh + (size_t)sj * F + lane * 2);
            }

            for (int bq = 0; bq < cnt; bq += 8) {
                unsigned rawn[8];
                bool more = (bq + 8 < cnt);
                if (more) {
                    #pragma unroll
                    for (int j = 0; j < 8; j++) {
                        int sj = __shfl_sync(0xFFFFFFFFu, sid, bq + 8 + j);
                        rawn[j] = *(const unsigned*)(xlh + (size_t)sj * F + lane * 2);
                    }
                }

                float2 av[8];
                float p[8];
                #pragma unroll
                for (int j = 0; j < 8; j++) {
                    av[j] = __half22float2(*(__half2*)&raw[j]);
                    float zx = av[j].x + xr2.x, zy = av[j].y + xr2.y;
                    p[j] = fmaf(at2.x, fabsf(zx), at2.y * fabsf(zy));
                    if (lane == bq + j) p[j] += pinit;
                }
                float q[4];
                #pragma unroll
                for (int k = 0; k < 4; k++) {
                    float sendv = h16 ? p[k] : p[k + 4];
                    float recv = __shfl_xor_sync(0xFFFFFFFFu, sendv, 16);
                    q[k] = (h16 ? p[k + 4] : p[k]) + recv;
                }
                float rr[2];
                #pragma unroll
                for (int k = 0; k < 2; k++) {
                    float sendv = h8 ? q[k] : q[k + 2];
                    float recv = __shfl_xor_sync(0xFFFFFFFFu, sendv, 8);
                    rr[k] = (h8 ? q[k + 2] : q[k]) + recv;
                }
                float sendv = h4 ? rr[0] : rr[1];
                float recv = __shfl_xor_sync(0xFFFFFFFFu, sendv, 4);
                float s = (h4 ? rr[1] : rr[0]) + recv;
                s += __shfl_xor_sync(0xFFFFFFFFu, s, 2);
                s += __shfl_xor_sync(0xFFFFFFFFu, s, 1);
                float w = __expf(fmaf(0.4f, s, -20.0f));
                #pragma unroll
                for (int j = 0; j < 8; j++) {
                    float wj = __shfl_sync(0xFFFFFFFFu, w, 4 * j);
                    wj = (bq + j < cnt) ? wj : 0.0f;
                    ssum += wj;
                    acc.x = fmaf(wj, av[j].x, acc.x);
                    acc.y = fmaf(wj, av[j].y, acc.y);
                }
                if (more) {
                    #pragma unroll
                    for (int j = 0; j < 8; j++) raw[j] = rawn[j];
                }
            }
        }
        float inv = 1.0f / (ssum + 1e-16f);
        float2 bb = *(const float2*)(bias + lane * 2);
        float v0 = acc.x * inv + bb.x, v1 = acc.y * inv + bb.y;
        if (RELU) { v0 = fmaxf(v0, 0.f); v1 = fmaxf(v1, 0.f); }
        *(float2*)(outp + (size_t)node * F + lane * 2) = make_float2(v0, v1);
    }
}

// ---------------------------------------------------------------------------
// Host launch (serial main stream + CSR/convert side streams)
// ---------------------------------------------------------------------------
extern "C" void kernel_launch(void* const* d_in, const int* in_sizes, int n_in,
                              void* d_out, int out_size) {
    const float* x    = (const float*)d_in[0];
    const int*   ei   = (const int*)d_in[1];
    const float* Wl1  = (const float*)d_in[2];
    const float* Wr1  = (const float*)d_in[3];
    const float* att1 = (const float*)d_in[4];
    const float* b1   = (const float*)d_in[5];
    const float* Wl2  = (const float*)d_in[6];
    const float* Wr2  = (const float*)d_in[7];
    const float* att2 = (const float*)d_in[8];
    const float* b2   = (const float*)d_in[9];
    float* out = (float*)d_out;

    int E = in_sizes[1] / 2;
    const int* srcp = ei;
    const int* dstp = ei + E;

    constexpr int SMEM128 = (3 * 128 * 24 * 2 + 3 * 16 * (128 + 8) * 2) * 2;  // 62976 B
    constexpr int SMEM64  = (3 * 128 * 24 * 2 + 3 * 16 * (64 + 8) * 2) * 2;   // 50688 B

    static cudaStream_t s2 = nullptr, s3 = nullptr;
    static cudaEvent_t e_fork, e_w1, e_w2, e_csr;
    if (!s2) {
        cudaStreamCreateWithFlags(&s2, cudaStreamNonBlocking);
        cudaStreamCreateWithFlags(&s3, cudaStreamNonBlocking);
        cudaEventCreateWithFlags(&e_fork, cudaEventDisableTiming);
        cudaEventCreateWithFlags(&e_w1,   cudaEventDisableTiming);
        cudaEventCreateWithFlags(&e_w2,   cudaEventDisableTiming);
        cudaEventCreateWithFlags(&e_csr,  cudaEventDisableTiming);
        cudaFuncSetAttribute((const void*)gemm_tc_kernel<128>,
                             cudaFuncAttributeMaxDynamicSharedMemorySize, SMEM128);
        cudaFuncSetAttribute((const void*)gemm_tc_kernel<64>,
                             cudaFuncAttributeMaxDynamicSharedMemorySize, SMEM64);
    }

    cudaStream_t m = 0;
    int eBlocks4 = (E + 1023) / 1024;
    int warpGrid = (NN * 32 + 255) / 256;

    cudaEventRecord(e_fork, m);
    cudaStreamWaitEvent(s2, e_fork, 0);
    cudaStreamWaitEvent(s3, e_fork, 0);

    // m: x convert
    cvt_kernel<<<(int)(((long long)NN * FIN / 4 + 255) / 256), 256, 0, m>>>(
        x, 0, 0, (long long)NN * FIN);

    // s3: weight converts
    cvt_kernel<<<32, 256, 0, s3>>>(Wl1, 1, 0, 32768);
    cvt_kernel<<<32, 256, 0, s3>>>(Wr1, 1, 32768, 32768);
    cudaEventRecord(e_w1, s3);
    cvt_kernel<<<8,  256, 0, s3>>>(Wl2, 1, 65536, 8192);
    cvt_kernel<<<8,  256, 0, s3>>>(Wr2, 1, 73728, 8192);
    cudaEventRecord(e_w2, s3);

    // m: merged layer-1 GEMM (L y=0 -> fp16 xl1 + g_dl, R y=1 -> fp32 xr1 + g_dr)
    cudaStreamWaitEvent(m, e_w1, 0);
    gemm_tc_kernel<128><<<dim3((NN + 127) / 128, 2), 256, SMEM128, m>>>(
        0, FIN, 0, 32768, OFF_XL1, (long long)NN * HH, HH, att1);

    // s2: CSR build (overlaps converts + gemm1)
    zero_cnt_kernel<<<NBLK, 256, 0, s2>>>();
    hist_kernel<<<eBlocks4, 256, 0, s2>>>(dstp, E);
    scan1_kernel<<<NBLK, 256, 0, s2>>>();
    scan2_kernel<<<1, 256, 0, s2>>>();
    scan3_kernel<<<NBLK, 256, 0, s2>>>(E);
    scatter_kernel<<<eBlocks4, 256, 0, s2>>>(srcp, dstp, E);
    cudaEventRecord(e_csr, s2);

    // m: node1 (fp16 gather, pipelined; emits h as bf16 hi/lo)
    cudaStreamWaitEvent(m, e_csr, 0);
    node_kernel<128, true, true><<<warpGrid, 256, 0, m>>>(
        OFF_XR1, att1, b1, nullptr);

    // m: merged layer-2 GEMM
    cudaStreamWaitEvent(m, e_w2, 0);
    gemm_tc_kernel<64><<<dim3((NN + 127) / 128, 2), 256, SMEM64, m>>>(
        1, HH, 65536, 8192, OFF_XL2, (long long)NN * CC, CC, att2);

    // m: node2 -> out (fp16 gather, pipelined)
    node_kernel<64, false, false><<<warpGrid, 256, 0, m>>>(
        OFF_XR2, att2, b2, out);
}

// round 14
// speedup vs baseline: 1.1263x; 1.1263x over previous
#include <cuda_runtime.h>
#include <cuda_bf16.h>
#include <cuda_fp16.h>
#include <math.h>

// ---------------------------------------------------------------------------
// Problem constants
// ---------------------------------------------------------------------------
#define NN   50000
#define FIN  256
#define HH   128
#define CC   64
#define EMAX 1600000
#define NBLK 196              // ceil(NN/256)

// ---------------------------------------------------------------------------
// Static scratch
// ---------------------------------------------------------------------------
constexpr long long OFF_XL1 = 0;
constexpr long long OFF_XR1 = (long long)NN * HH;
constexpr long long OFF_XL2 = 2LL * NN * HH;
constexpr long long OFF_XR2 = OFF_XL2 + (long long)NN * CC;
constexpr long long POOL_SZ = OFF_XR2 + (long long)NN * CC;

__device__ float g_pool[POOL_SZ];

__device__ __nv_bfloat16 g_xhi[(long long)NN * FIN];
__device__ __nv_bfloat16 g_xlo[(long long)NN * FIN];
__device__ __nv_bfloat16 g_hhi[(long long)NN * HH];
__device__ __nv_bfloat16 g_hlo[(long long)NN * HH];
// packed weights: W1L @0 (32768), W1R @32768, W2L @65536 (8192), W2R @73728
__device__ __nv_bfloat16 g_whi[81920];
__device__ __nv_bfloat16 g_wlo[81920];

// fp16 gather operands for node kernels (xl transforms)
__device__ __half g_xl1h[(long long)NN * HH];
__device__ __half g_xl2h[(long long)NN * CC];

__device__ float g_dl[NN];
__device__ float g_dr[NN];

__device__ int g_cnt[NN];
__device__ int g_off[NN + 1];
__device__ int g_cur[NN];
__device__ int g_bsum[256];
__device__ int g_ssrc[EMAX];

// ---------------------------------------------------------------------------
// fp32 -> bf16 hi/lo conversion
// ---------------------------------------------------------------------------
__global__ void cvt_kernel(const float* __restrict__ src, int sel,
                           long long doff, long long n) {
    __nv_bfloat16* hi = sel ? g_whi : g_xhi;
    __nv_bfloat16* lo = sel ? g_wlo : g_xlo;
    long long i = ((long long)blockIdx.x * blockDim.x + threadIdx.x) * 4;
    if (i >= n) return;
    float4 v = *(const float4*)(src + i);
    float vv[4] = {v.x, v.y, v.z, v.w};
    __nv_bfloat16 h[4], l[4];
    #pragma unroll
    for (int j = 0; j < 4; j++) {
        h[j] = __float2bfloat16(vv[j]);
        l[j] = __float2bfloat16(vv[j] - __bfloat162float(h[j]));
    }
    *(__nv_bfloat162*)(hi + doff + i)     = __nv_bfloat162(h[0], h[1]);
    *(__nv_bfloat162*)(hi + doff + i + 2) = __nv_bfloat162(h[2], h[3]);
    *(__nv_bfloat162*)(lo + doff + i)     = __nv_bfloat162(l[0], l[1]);
    *(__nv_bfloat162*)(lo + doff + i + 2) = __nv_bfloat162(l[2], l[3]);
}

// ---------------------------------------------------------------------------
// CSR construction
// ---------------------------------------------------------------------------
__global__ void zero_cnt_kernel() {
    int i = blockIdx.x * blockDim.x + threadIdx.x;
    if (i < NN) g_cnt[i] = 0;
}

__global__ void hist_kernel(const int* __restrict__ dst, int E) {
    int i0 = (blockIdx.x * blockDim.x + threadIdx.x) * 4;
    #pragma unroll
    for (int j = 0; j < 4; j++) {
        int i = i0 + j;
        if (i < E) atomicAdd(&g_cnt[dst[i]], 1);
    }
}

__global__ void scan1_kernel() {
    __shared__ int wt[8];
    int t = threadIdx.x, lane = t & 31, wid = t >> 5;
    int idx = blockIdx.x * 256 + t;
    int v = (idx < NN) ? g_cnt[idx] : 0;
    int x = v;
    #pragma unroll
    for (int o = 1; o < 32; o <<= 1) {
        int tmp = __shfl_up_sync(0xFFFFFFFFu, x, o);
        if (lane >= o) x += tmp;
    }
    if (lane == 31) wt[wid] = x;
    __syncthreads();
    if (wid == 0 && lane < 8) {
        int w = wt[lane], wx = w;
        #pragma unroll
        for (int o = 1; o < 8; o <<= 1) {
            int tmp = __shfl_up_sync(0xFFu, wx, o);
            if (lane >= o) wx += tmp;
        }
        wt[lane] = wx - w;
    }
    __syncthreads();
    int excl = x - v + wt[wid];
    if (idx < NN) g_off[idx] = excl;
    if (t == 255) g_bsum[blockIdx.x] = excl + v;
}

__global__ void scan2_kernel() {
    __shared__ int wt[8];
    int t = threadIdx.x, lane = t & 31, wid = t >> 5;
    int v = (t < NBLK) ? g_bsum[t] : 0;
    int x = v;
    #pragma unroll
    for (int o = 1; o < 32; o <<= 1) {
        int tmp = __shfl_up_sync(0xFFFFFFFFu, x, o);
        if (lane >= o) x += tmp;
    }
    if (lane == 31) wt[wid] = x;
    __syncthreads();
    if (wid == 0 && lane < 8) {
        int w = wt[lane], wx = w;
        #pragma unroll
        for (int o = 1; o < 8; o <<= 1) {
            int tmp = __shfl_up_sync(0xFFu, wx, o);
            if (lane >= o) wx += tmp;
        }
        wt[lane] = wx - w;
    }
    __syncthreads();
    if (t < NBLK) g_bsum[t] = x - v + wt[wid];
}

__global__ void scan3_kernel(int E) {
    int idx = blockIdx.x * 256 + threadIdx.x;
    if (idx < NN) {
        int o = g_off[idx] + g_bsum[blockIdx.x];
        g_off[idx] = o;
        g_cur[idx] = o;
    }
    if (idx == 0) g_off[NN] = E;
}

__global__ void scatter_kernel(const int* __restrict__ src,
                               const int* __restrict__ dst, int E) {
    int i0 = (blockIdx.x * blockDim.x + threadIdx.x) * 4;
    #pragma unroll
    for (int j = 0; j < 4; j++) {
        int i = i0 + j;
        if (i < E) {
            int pos = atomicAdd(&g_cur[dst[i]], 1);
            g_ssrc[pos] = src[i];
        }
    }
}

// ---------------------------------------------------------------------------
// Tensor-core GEMM, bf16 hi/lo, 3-stage cp.async pipeline, merged L/R via
// blockIdx.y, fused att-dot epilogue (-> g_dl y=0, g_dr y=1).
// y==0 (L operand) emits fp16 xl instead of fp32 C (node kernels gather fp16).
// ---------------------------------------------------------------------------
__device__ __forceinline__ void ldsm_x4(unsigned* r, unsigned addr) {
    asm volatile("ldmatrix.sync.aligned.m8n8.x4.shared.b16 {%0,%1,%2,%3}, [%4];"
                 : "=r"(r[0]), "=r"(r[1]), "=r"(r[2]), "=r"(r[3]) : "r"(addr));
}
__device__ __forceinline__ void ldsm_x4t(unsigned* r, unsigned addr) {
    asm volatile("ldmatrix.sync.aligned.m8n8.x4.trans.shared.b16 {%0,%1,%2,%3}, [%4];"
                 : "=r"(r[0]), "=r"(r[1]), "=r"(r[2]), "=r"(r[3]) : "r"(addr));
}
__device__ __forceinline__ void mma_bf16(float* c, const unsigned* a, const unsigned* b) {
    asm volatile(
        "mma.sync.aligned.m16n8k16.row.col.f32.bf16.bf16.f32 "
        "{%0,%1,%2,%3}, {%4,%5,%6,%7}, {%8,%9}, {%0,%1,%2,%3};"
        : "+f"(c[0]), "+f"(c[1]), "+f"(c[2]), "+f"(c[3])
        : "r"(a[0]), "r"(a[1]), "r"(a[2]), "r"(a[3]), "r"(b[0]), "r"(b[1]));
}
__device__ __forceinline__ void cp16(unsigned dst, const void* src, bool valid) {
    int sz = valid ? 16 : 0;
    asm volatile("cp.async.cg.shared.global [%0], [%1], 16, %2;"
                 :: "r"(dst), "l"(src), "r"(sz));
}
#define CP_COMMIT() asm volatile("cp.async.commit_group;")
#define CP_WAIT1()  asm volatile("cp.async.wait_group 1;")
#define CP_WAIT0()  asm volatile("cp.async.wait_group 0;")

template<int TN>
__global__ __launch_bounds__(256)
void gemm_tc_kernel(int a_sel, int K, long long w_off0, long long w_stride,
                    long long c_off0, long long c_stride, int Fout,
                    const float* __restrict__ att) {
    constexpr int TM = 128, BK = 16;
    constexpr int APITCH = 24;
    constexpr int BPITCH = TN + 8;
    constexpr int NF = TN / 32;
    constexpr int ASTAGE = TM * APITCH;
    constexpr int BSTAGE = BK * BPITCH;

    const __nv_bfloat16* Ahi = a_sel ? g_hhi : g_xhi;
    const __nv_bfloat16* Alo = a_sel ? g_hlo : g_xlo;
    long long w_off = w_off0 + (long long)blockIdx.y * w_stride;
    const __nv_bfloat16* Whi = g_whi + w_off;
    const __nv_bfloat16* Wlo = g_wlo + w_off;
    float* C = g_pool + c_off0 + (long long)blockIdx.y * c_stride;
    float* dots = blockIdx.y ? g_dr : g_dl;
    bool isL = (blockIdx.y == 0);
    __half* xh = a_sel ? g_xl2h : g_xl1h;

    extern __shared__ __align__(16) __nv_bfloat16 sm[];
    __nv_bfloat16* Ah = sm;
    __nv_bfloat16* Al = Ah + 3 * ASTAGE;
    __nv_bfloat16* Bh = Al + 3 * ASTAGE;
    __nv_bfloat16* Bl = Bh + 3 * BSTAGE;
    float* sdot = (float*)sm;          // reused after mainloop

    int t = threadIdx.x;
    int lane = t & 31, wid = t >> 5;
    int warp_m = wid & 1, warp_n = wid >> 1;
    int m_off = warp_m * 64, n_off = warp_n * (TN / 4);
    int row0 = blockIdx.x * TM;
    int N = NN;

    float c[4][NF][4];
    #pragma unroll
    for (int i = 0; i < 4; i++)
        #pragma unroll
        for (int j = 0; j < NF; j++)
            #pragma unroll
            for (int q = 0; q < 4; q++) c[i][j][q] = 0.0f;

    int g = lane >> 3, r = lane & 7;
    int a_row = (g & 1) * 8 + r;
    int a_col = (g >> 1) * 8;
    int b_krow = lane & 15;
    int b_chalf = (lane >> 4) * 8;

    int am = t >> 1;
    int ac = (t & 1) * 8;

    const int NIT = K / BK;

    auto load_stage = [&](int it, int s) {
        int k0 = it * BK;
        int grow = row0 + am;
        bool v = grow < N;
        cp16((unsigned)__cvta_generic_to_shared(Ah + s * ASTAGE + am * APITCH + ac),
             Ahi + (size_t)grow * K + k0 + ac, v);
        cp16((unsigned)__cvta_generic_to_shared(Al + s * ASTAGE + am * APITCH + ac),
             Alo + (size_t)grow * K + k0 + ac, v);
        if (TN == 128) {
            int kk = t >> 4, ch = (t & 15) * 8;
            cp16((unsigned)__cvta_generic_to_shared(Bh + s * BSTAGE + kk * BPITCH + ch),
                 Whi + (size_t)(k0 + kk) * Fout + ch, true);
            cp16((unsigned)__cvta_generic_to_shared(Bl + s * BSTAGE + kk * BPITCH + ch),
                 Wlo + (size_t)(k0 + kk) * Fout + ch, true);
        } else {
            if (t < 128) {
                int kk = t >> 3, ch = (t & 7) * 8;
                cp16((unsigned)__cvta_generic_to_shared(Bh + s * BSTAGE + kk * BPITCH + ch),
                     Whi + (size_t)(k0 + kk) * Fout + ch, true);
                cp16((unsigned)__cvta_generic_to_shared(Bl + s * BSTAGE + kk * BPITCH + ch),
                     Wlo + (size_t)(k0 + kk) * Fout + ch, true);
            }
        }
    };

    load_stage(0, 0);
    CP_COMMIT();
    if (NIT > 1) load_stage(1, 1);
    CP_COMMIT();

    for (int it = 0; it < NIT; it++) {
        CP_WAIT1();
        __syncthreads();
        if (it + 2 < NIT) load_stage(it + 2, (it + 2) % 3);
        CP_COMMIT();

        int s = it % 3;
        unsigned ah[4][4], bh[NF][2];
        #pragma unroll
        for (int i = 0; i < 4; i++)
            ldsm_x4(ah[i], (unsigned)__cvta_generic_to_shared(
                        Ah + s * ASTAGE + (m_off + i * 16 + a_row) * APITCH + a_col));
        #pragma unroll
        for (int j = 0; j < NF; j += 2)
            ldsm_x4t(&bh[j][0], (unsigned)__cvta_generic_to_shared(
                        Bh + s * BSTAGE + b_krow * BPITCH + n_off + j * 8 + b_chalf));
        #pragma unroll
        for (int i = 0; i < 4; i++)
            #pragma unroll
            for (int j = 0; j < NF; j++) mma_bf16(c[i][j], ah[i], bh[j]);

        unsigned bl[NF][2];
        #pragma unroll
        for (int j = 0; j < NF; j += 2)
            ldsm_x4t(&bl[j][0], (unsigned)__cvta_generic_to_shared(
                        Bl + s * BSTAGE + b_krow * BPITCH + n_off + j * 8 + b_chalf));
        #pragma unroll
        for (int i = 0; i < 4; i++)
            #pragma unroll
            for (int j = 0; j < NF; j++) mma_bf16(c[i][j], ah[i], bl[j]);

        unsigned al[4][4];
        #pragma unroll
        for (int i = 0; i < 4; i++)
            ldsm_x4(al[i], (unsigned)__cvta_generic_to_shared(
                        Al + s * ASTAGE + (m_off + i * 16 + a_row) * APITCH + a_col));
        #pragma unroll
        for (int i = 0; i < 4; i++)
            #pragma unroll
            for (int j = 0; j < NF; j++) mma_bf16(c[i][j], al[i], bh[j]);
    }

    // ---- epilogue: stores (fp16 xl for L, fp32 for R) + fused att-dot ----
    CP_WAIT0();
    __syncthreads();                 // all ldsm reads done; smem reusable
    if (t < TM) sdot[t] = 0.0f;
    __syncthreads();

    int lr = lane >> 2;
    int lc = (lane & 3) * 2;
    #pragma unroll
    for (int i = 0; i < 4; i++) {
        int gr = row0 + m_off + i * 16 + lr;
        float p0 = 0.0f, p1 = 0.0f;
        #pragma unroll
        for (int j = 0; j < NF; j++) {
            int gc = n_off + j * 8 + lc;
            float a0 = att[gc], a1 = att[gc + 1];
            if (gr < N) {
                if (isL)
                    *(__half2*)(xh + (size_t)gr * Fout + gc) =
                        __floats2half2_rn(c[i][j][0], c[i][j][1]);
                else
                    *(float2*)(C + (size_t)gr * Fout + gc) =
                        make_float2(c[i][j][0], c[i][j][1]);
            }
            if (gr + 8 < N) {
                if (isL)
                    *(__half2*)(xh + (size_t)(gr + 8) * Fout + gc) =
                        __floats2half2_rn(c[i][j][2], c[i][j][3]);
                else
                    *(float2*)(C + (size_t)(gr + 8) * Fout + gc) =
                        make_float2(c[i][j][2], c[i][j][3]);
            }
            p0 = fmaf(c[i][j][0], a0, fmaf(c[i][j][1], a1, p0));
            p1 = fmaf(c[i][j][2], a0, fmaf(c[i][j][3], a1, p1));
        }
        atomicAdd(&sdot[m_off + i * 16 + lr], p0);
        atomicAdd(&sdot[m_off + i * 16 + lr + 8], p1);
    }
    __syncthreads();
    if (t < TM && row0 + t < N) dots[row0 + t] = sdot[t];
}

// ---------------------------------------------------------------------------
// Fused per-node kernel: warp/node, constant-shift softmax, batched 8-edge
// split-tree reduction. xl gather from fp16 (half the bytes).
// ---------------------------------------------------------------------------
template<int F, bool RELU, bool EMIT_BF16>
__global__ __launch_bounds__(256)
void node_kernel(long long xr_off,
                 const float* __restrict__ att,
                 const float* __restrict__ bias,
                 float* __restrict__ outp) {
    int node = (int)(((long long)blockIdx.x * blockDim.x + threadIdx.x) >> 5);
    int lane = threadIdx.x & 31;
    if (node >= NN) return;

    const __half* xlh = (F == 128) ? g_xl1h : g_xl2h;
    const float* xr = g_pool + xr_off;
    int s0 = g_off[node], s1 = g_off[node + 1];
    float dr = g_dr[node];
    bool h16 = (lane & 16) != 0;
    bool h8  = (lane & 8)  != 0;
    bool h4  = (lane & 4)  != 0;

    if (F == 128) {
        float4 xr4 = *(const float4*)(xr + (size_t)node * F + lane * 4);
        float4 at4 = *(const float4*)(att + lane * 4);
        float4 acc = make_float4(0.f, 0.f, 0.f, 0.f);
        float ssum = 0.0f;

        for (int base = s0; base < s1; base += 32) {
            int cnt = min(32, s1 - base);
            int safe = min(base + lane, s1 - 1);
            int sid = g_ssrc[safe];
            float pinit = 1.5f * (g_dl[sid] + dr);

            for (int bq = 0; bq < cnt; bq += 8) {
                float4 av[8];
                float p[8];
                #pragma unroll
                for (int j = 0; j < 8; j++) {
                    int sj = __shfl_sync(0xFFFFFFFFu, sid, bq + j);
                    uint2 raw = *(const uint2*)(xlh + (size_t)sj * F + lane * 4);
                    float2 f01 = __half22float2(*(__half2*)&raw.x);
                    float2 f23 = __half22float2(*(__half2*)&raw.y);
                    av[j] = make_float4(f01.x, f01.y, f23.x, f23.y);
                    float zx = av[j].x + xr4.x, zy = av[j].y + xr4.y;
                    float zz = av[j].z + xr4.z, zw = av[j].w + xr4.w;
                    p[j] = fmaf(at4.x, fabsf(zx),
                           fmaf(at4.y, fabsf(zy),
                           fmaf(at4.z, fabsf(zz), at4.w * fabsf(zw))));
                    if (lane == bq + j) p[j] += pinit;
                }
                // split-tree reduce: 9 shfl for 8 edge sums
                float q[4];
                #pragma unroll
                for (int k = 0; k < 4; k++) {
                    float sendv = h16 ? p[k] : p[k + 4];
                    float recv = __shfl_xor_sync(0xFFFFFFFFu, sendv, 16);
                    q[k] = (h16 ? p[k + 4] : p[k]) + recv;
                }
                float rr[2];
                #pragma unroll
                for (int k = 0; k < 2; k++) {
                    float sendv = h8 ? q[k] : q[k + 2];
                    float recv = __shfl_xor_sync(0xFFFFFFFFu, sendv, 8);
                    rr[k] = (h8 ? q[k + 2] : q[k]) + recv;
                }
                float sendv = h4 ? rr[0] : rr[1];
                float recv = __shfl_xor_sync(0xFFFFFFFFu, sendv, 4);
                float s = (h4 ? rr[1] : rr[0]) + recv;
                s += __shfl_xor_sync(0xFFFFFFFFu, s, 2);
                s += __shfl_xor_sync(0xFFFFFFFFu, s, 1);
                float w = __expf(fmaf(0.4f, s, -20.0f));
                #pragma unroll
                for (int j = 0; j < 8; j++) {
                    float wj = __shfl_sync(0xFFFFFFFFu, w, 4 * j);
                    wj = (bq + j < cnt) ? wj : 0.0f;
                    ssum += wj;
                    acc.x = fmaf(wj, av[j].x, acc.x);
                    acc.y = fmaf(wj, av[j].y, acc.y);
                    acc.z = fmaf(wj, av[j].z, acc.z);
                    acc.w = fmaf(wj, av[j].w, acc.w);
                }
            }
        }
        float inv = 1.0f / (ssum + 1e-16f);
        float4 bb = *(const float4*)(bias + lane * 4);
        float v0 = acc.x * inv + bb.x, v1 = acc.y * inv + bb.y;
        float v2 = acc.z * inv + bb.z, v3 = acc.w * inv + bb.w;
        if (RELU) {
            v0 = fmaxf(v0, 0.f); v1 = fmaxf(v1, 0.f);
            v2 = fmaxf(v2, 0.f); v3 = fmaxf(v3, 0.f);
        }
        if (EMIT_BF16) {
            size_t o = (size_t)node * F + lane * 4;
            __nv_bfloat16 h0 = __float2bfloat16(v0), h1 = __float2bfloat16(v1);
            __nv_bfloat16 h2 = __float2bfloat16(v2), h3 = __float2bfloat16(v3);
            *(__nv_bfloat162*)(g_hhi + o)     = __nv_bfloat162(h0, h1);
            *(__nv_bfloat162*)(g_hhi + o + 2) = __nv_bfloat162(h2, h3);
            *(__nv_bfloat162*)(g_hlo + o) = __nv_bfloat162(
                __float2bfloat16(v0 - __bfloat162float(h0)),
                __float2bfloat16(v1 - __bfloat162float(h1)));
            *(__nv_bfloat162*)(g_hlo + o + 2) = __nv_bfloat162(
                __float2bfloat16(v2 - __bfloat162float(h2)),
                __float2bfloat16(v3 - __bfloat162float(h3)));
        } else {
            *(float4*)(outp + (size_t)node * F + lane * 4) = make_float4(v0, v1, v2, v3);
        }
    } else { // F == 64
        float2 xr2 = *(const float2*)(xr + (size_t)node * F + lane * 2);
        float2 at2 = *(const float2*)(att + lane * 2);
        float2 acc = make_float2(0.f, 0.f);
        float ssum = 0.0f;

        for (int base = s0; base < s1; base += 32) {
            int cnt = min(32, s1 - base);
            int safe = min(base + lane, s1 - 1);
            int sid = g_ssrc[safe];
            float pinit = 1.5f * (g_dl[sid] + dr);

            for (int bq = 0; bq < cnt; bq += 8) {
                float2 av[8];
                float p[8];
                #pragma unroll
                for (int j = 0; j < 8; j++) {
                    int sj = __shfl_sync(0xFFFFFFFFu, sid, bq + j);
                    unsigned raw = *(const unsigned*)(xlh + (size_t)sj * F + lane * 2);
                    av[j] = __half22float2(*(__half2*)&raw);
                    float zx = av[j].x + xr2.x, zy = av[j].y + xr2.y;
                    p[j] = fmaf(at2.x, fabsf(zx), at2.y * fabsf(zy));
                    if (lane == bq + j) p[j] += pinit;
                }
                float q[4];
                #pragma unroll
                for (int k = 0; k < 4; k++) {
                    float sendv = h16 ? p[k] : p[k + 4];
                    float recv = __shfl_xor_sync(0xFFFFFFFFu, sendv, 16);
                    q[k] = (h16 ? p[k + 4] : p[k]) + recv;
                }
                float rr[2];
                #pragma unroll
                for (int k = 0; k < 2; k++) {
                    float sendv = h8 ? q[k] : q[k + 2];
                    float recv = __shfl_xor_sync(0xFFFFFFFFu, sendv, 8);
                    rr[k] = (h8 ? q[k + 2] : q[k]) + recv;
                }
                float sendv = h4 ? rr[0] : rr[1];
                float recv = __shfl_xor_sync(0xFFFFFFFFu, sendv, 4);
                float s = (h4 ? rr[1] : rr[0]) + recv;
                s += __shfl_xor_sync(0xFFFFFFFFu, s, 2);
                s += __shfl_xor_sync(0xFFFFFFFFu, s, 1);
                float w = __expf(fmaf(0.4f, s, -20.0f));
                #pragma unroll
                for (int j = 0; j < 8; j++) {
                    float wj = __shfl_sync(0xFFFFFFFFu, w, 4 * j);
                    wj = (bq + j < cnt) ? wj : 0.0f;
                    ssum += wj;
                    acc.x = fmaf(wj, av[j].x, acc.x);
                    acc.y = fmaf(wj, av[j].y, acc.y);
                }
            }
        }
        float inv = 1.0f / (ssum + 1e-16f);
        float2 bb = *(const float2*)(bias + lane * 2);
        float v0 = acc.x * inv + bb.x, v1 = acc.y * inv + bb.y;
        if (RELU) { v0 = fmaxf(v0, 0.f); v1 = fmaxf(v1, 0.f); }
        *(float2*)(outp + (size_t)node * F + lane * 2) = make_float2(v0, v1);
    }
}

// ---------------------------------------------------------------------------
// Host launch (serial main stream + CSR/convert side streams)
// ---------------------------------------------------------------------------
extern "C" void kernel_launch(void* const* d_in, const int* in_sizes, int n_in,
                              void* d_out, int out_size) {
    const float* x    = (const float*)d_in[0];
    const int*   ei   = (const int*)d_in[1];
    const float* Wl1  = (const float*)d_in[2];
    const float* Wr1  = (const float*)d_in[3];
    const float* att1 = (const float*)d_in[4];
    const float* b1   = (const float*)d_in[5];
    const float* Wl2  = (const float*)d_in[6];
    const float* Wr2  = (const float*)d_in[7];
    const float* att2 = (const float*)d_in[8];
    const float* b2   = (const float*)d_in[9];
    float* out = (float*)d_out;

    int E = in_sizes[1] / 2;
    const int* srcp = ei;
    const int* dstp = ei + E;

    constexpr int SMEM128 = (3 * 128 * 24 * 2 + 3 * 16 * (128 + 8) * 2) * 2;  // 62976 B
    constexpr int SMEM64  = (3 * 128 * 24 * 2 + 3 * 16 * (64 + 8) * 2) * 2;   // 50688 B

    static cudaStream_t s2 = nullptr, s3 = nullptr;
    static cudaEvent_t e_fork, e_w1, e_w2, e_csr;
    if (!s2) {
        cudaStreamCreateWithFlags(&s2, cudaStreamNonBlocking);
        cudaStreamCreateWithFlags(&s3, cudaStreamNonBlocking);
        cudaEventCreateWithFlags(&e_fork, cudaEventDisableTiming);
        cudaEventCreateWithFlags(&e_w1,   cudaEventDisableTiming);
        cudaEventCreateWithFlags(&e_w2,   cudaEventDisableTiming);
        cudaEventCreateWithFlags(&e_csr,  cudaEventDisableTiming);
        cudaFuncSetAttribute((const void*)gemm_tc_kernel<128>,
                             cudaFuncAttributeMaxDynamicSharedMemorySize, SMEM128);
        cudaFuncSetAttribute((const void*)gemm_tc_kernel<64>,
                             cudaFuncAttributeMaxDynamicSharedMemorySize, SMEM64);
    }

    cudaStream_t m = 0;
    int eBlocks4 = (E + 1023) / 1024;
    int warpGrid = (NN * 32 + 255) / 256;

    cudaEventRecord(e_fork, m);
    cudaStreamWaitEvent(s2, e_fork, 0);
    cudaStreamWaitEvent(s3, e_fork, 0);

    // m: x convert
    cvt_kernel<<<(int)(((long long)NN * FIN / 4 + 255) / 256), 256, 0, m>>>(
        x, 0, 0, (long long)NN * FIN);

    // s3: weight converts
    cvt_kernel<<<32, 256, 0, s3>>>(Wl1, 1, 0, 32768);
    cvt_kernel<<<32, 256, 0, s3>>>(Wr1, 1, 32768, 32768);
    cudaEventRecord(e_w1, s3);
    cvt_kernel<<<8,  256, 0, s3>>>(Wl2, 1, 65536, 8192);
    cvt_kernel<<<8,  256, 0, s3>>>(Wr2, 1, 73728, 8192);
    cudaEventRecord(e_w2, s3);

    // m: merged layer-1 GEMM (L y=0 -> fp16 xl1 + g_dl, R y=1 -> fp32 xr1 + g_dr)
    cudaStreamWaitEvent(m, e_w1, 0);
    gemm_tc_kernel<128><<<dim3((NN + 127) / 128, 2), 256, SMEM128, m>>>(
        0, FIN, 0, 32768, OFF_XL1, (long long)NN * HH, HH, att1);

    // s2: CSR build (overlaps converts + gemm1)
    zero_cnt_kernel<<<NBLK, 256, 0, s2>>>();
    hist_kernel<<<eBlocks4, 256, 0, s2>>>(dstp, E);
    scan1_kernel<<<NBLK, 256, 0, s2>>>();
    scan2_kernel<<<1, 256, 0, s2>>>();
    scan3_kernel<<<NBLK, 256, 0, s2>>>(E);
    scatter_kernel<<<eBlocks4, 256, 0, s2>>>(srcp, dstp, E);
    cudaEventRecord(e_csr, s2);

    // m: node1 (fp16 gather; emits h as bf16 hi/lo)
    cudaStreamWaitEvent(m, e_csr, 0);
    node_kernel<128, true, true><<<warpGrid, 256, 0, m>>>(
        OFF_XR1, att1, b1, nullptr);

    // m: merged layer-2 GEMM
    cudaStreamWaitEvent(m, e_w2, 0);
    gemm_tc_kernel<64><<<dim3((NN + 127) / 128, 2), 256, SMEM64, m>>>(
        1, HH, 65536, 8192, OFF_XL2, (long long)NN * CC, CC, att2);

    // m: node2 -> out (fp16 gather)
    node_kernel<64, false, false><<<warpGrid, 256, 0, m>>>(
        OFF_XR2, att2, b2, out);
}

// round 15
// speedup vs baseline: 1.1665x; 1.0356x over previous
#include <cuda_runtime.h>
#include <cuda_bf16.h>
#include <cuda_fp16.h>
#include <math.h>

// ---------------------------------------------------------------------------
// Problem constants
// ---------------------------------------------------------------------------
#define NN   50000
#define FIN  256
#define HH   128
#define CC   64
#define EMAX 1600000
#define NBLK 196              // ceil(NN/256)

// ---------------------------------------------------------------------------
// Static scratch
// ---------------------------------------------------------------------------
constexpr long long OFF_XL1 = 0;
constexpr long long OFF_XR1 = (long long)NN * HH;
constexpr long long OFF_XL2 = 2LL * NN * HH;
constexpr long long OFF_XR2 = OFF_XL2 + (long long)NN * CC;
constexpr long long POOL_SZ = OFF_XR2 + (long long)NN * CC;

__device__ float g_pool[POOL_SZ];

__device__ __nv_bfloat16 g_xhi[(long long)NN * FIN];
__device__ __nv_bfloat16 g_xlo[(long long)NN * FIN];
__device__ __nv_bfloat16 g_hhi[(long long)NN * HH];
__device__ __nv_bfloat16 g_hlo[(long long)NN * HH];
// packed weights: W1L @0 (32768), W1R @32768, W2L @65536 (8192), W2R @73728
__device__ __nv_bfloat16 g_whi[81920];
__device__ __nv_bfloat16 g_wlo[81920];

// fp16 gather operands for node kernels (xl transforms)
__device__ __half g_xl1h[(long long)NN * HH];
__device__ __half g_xl2h[(long long)NN * CC];

__device__ float g_dl[NN];
__device__ float g_dr[NN];

__device__ int g_cnt[NN];
__device__ int g_off[NN + 1];
__device__ int g_cur[NN];
__device__ int g_bsum[256];
__device__ int g_ssrc[EMAX];

// ---------------------------------------------------------------------------
// fp32 -> bf16 hi/lo conversion
// ---------------------------------------------------------------------------
__global__ void cvt_kernel(const float* __restrict__ src, int sel,
                           long long doff, long long n) {
    __nv_bfloat16* hi = sel ? g_whi : g_xhi;
    __nv_bfloat16* lo = sel ? g_wlo : g_xlo;
    long long i = ((long long)blockIdx.x * blockDim.x + threadIdx.x) * 4;
    if (i >= n) return;
    float4 v = *(const float4*)(src + i);
    float vv[4] = {v.x, v.y, v.z, v.w};
    __nv_bfloat16 h[4], l[4];
    #pragma unroll
    for (int j = 0; j < 4; j++) {
        h[j] = __float2bfloat16(vv[j]);
        l[j] = __float2bfloat16(vv[j] - __bfloat162float(h[j]));
    }
    *(__nv_bfloat162*)(hi + doff + i)     = __nv_bfloat162(h[0], h[1]);
    *(__nv_bfloat162*)(hi + doff + i + 2) = __nv_bfloat162(h[2], h[3]);
    *(__nv_bfloat162*)(lo + doff + i)     = __nv_bfloat162(l[0], l[1]);
    *(__nv_bfloat162*)(lo + doff + i + 2) = __nv_bfloat162(l[2], l[3]);
}

// ---------------------------------------------------------------------------
// CSR construction
// ---------------------------------------------------------------------------
__global__ void zero_cnt_kernel() {
    int i = blockIdx.x * blockDim.x + threadIdx.x;
    if (i < NN) g_cnt[i] = 0;
}

__global__ void hist_kernel(const int* __restrict__ dst, int E) {
    int i0 = (blockIdx.x * blockDim.x + threadIdx.x) * 4;
    #pragma unroll
    for (int j = 0; j < 4; j++) {
        int i = i0 + j;
        if (i < E) atomicAdd(&g_cnt[dst[i]], 1);
    }
}

__global__ void scan1_kernel() {
    __shared__ int wt[8];
    int t = threadIdx.x, lane = t & 31, wid = t >> 5;
    int idx = blockIdx.x * 256 + t;
    int v = (idx < NN) ? g_cnt[idx] : 0;
    int x = v;
    #pragma unroll
    for (int o = 1; o < 32; o <<= 1) {
        int tmp = __shfl_up_sync(0xFFFFFFFFu, x, o);
        if (lane >= o) x += tmp;
    }
    if (lane == 31) wt[wid] = x;
    __syncthreads();
    if (wid == 0 && lane < 8) {
        int w = wt[lane], wx = w;
        #pragma unroll
        for (int o = 1; o < 8; o <<= 1) {
            int tmp = __shfl_up_sync(0xFFu, wx, o);
            if (lane >= o) wx += tmp;
        }
        wt[lane] = wx - w;
    }
    __syncthreads();
    int excl = x - v + wt[wid];
    if (idx < NN) g_off[idx] = excl;
    if (t == 255) g_bsum[blockIdx.x] = excl + v;
}

__global__ void scan2_kernel() {
    __shared__ int wt[8];
    int t = threadIdx.x, lane = t & 31, wid = t >> 5;
    int v = (t < NBLK) ? g_bsum[t] : 0;
    int x = v;
    #pragma unroll
    for (int o = 1; o < 32; o <<= 1) {
        int tmp = __shfl_up_sync(0xFFFFFFFFu, x, o);
        if (lane >= o) x += tmp;
    }
    if (lane == 31) wt[wid] = x;
    __syncthreads();
    if (wid == 0 && lane < 8) {
        int w = wt[lane], wx = w;
        #pragma unroll
        for (int o = 1; o < 8; o <<= 1) {
            int tmp = __shfl_up_sync(0xFFu, wx, o);
            if (lane >= o) wx += tmp;
        }
        wt[lane] = wx - w;
    }
    __syncthreads();
    if (t < NBLK) g_bsum[t] = x - v + wt[wid];
}

__global__ void scan3_kernel(int E) {
    int idx = blockIdx.x * 256 + threadIdx.x;
    if (idx < NN) {
        int o = g_off[idx] + g_bsum[blockIdx.x];
        g_off[idx] = o;
        g_cur[idx] = o;
    }
    if (idx == 0) g_off[NN] = E;
}

__global__ void scatter_kernel(const int* __restrict__ src,
                               const int* __restrict__ dst, int E) {
    int i0 = (blockIdx.x * blockDim.x + threadIdx.x) * 4;
    #pragma unroll
    for (int j = 0; j < 4; j++) {
        int i = i0 + j;
        if (i < E) {
            int pos = atomicAdd(&g_cur[dst[i]], 1);
            g_ssrc[pos] = src[i];
        }
    }
}

// ---------------------------------------------------------------------------
// Tensor-core GEMM, bf16 hi/lo, 3-stage cp.async pipeline, merged L/R via
// blockIdx.y, fused att-dot epilogue (-> g_dl y=0, g_dr y=1).
// y==0 (L operand) emits fp16 xl instead of fp32 C (node kernels gather fp16).
// Epilogue dot uses intra-warp butterfly pre-reduction (4x fewer smem atomics).
// ---------------------------------------------------------------------------
__device__ __forceinline__ void ldsm_x4(unsigned* r, unsigned addr) {
    asm volatile("ldmatrix.sync.aligned.m8n8.x4.shared.b16 {%0,%1,%2,%3}, [%4];"
                 : "=r"(r[0]), "=r"(r[1]), "=r"(r[2]), "=r"(r[3]) : "r"(addr));
}
__device__ __forceinline__ void ldsm_x4t(unsigned* r, unsigned addr) {
    asm volatile("ldmatrix.sync.aligned.m8n8.x4.trans.shared.b16 {%0,%1,%2,%3}, [%4];"
                 : "=r"(r[0]), "=r"(r[1]), "=r"(r[2]), "=r"(r[3]) : "r"(addr));
}
__device__ __forceinline__ void mma_bf16(float* c, const unsigned* a, const unsigned* b) {
    asm volatile(
        "mma.sync.aligned.m16n8k16.row.col.f32.bf16.bf16.f32 "
        "{%0,%1,%2,%3}, {%4,%5,%6,%7}, {%8,%9}, {%0,%1,%2,%3};"
        : "+f"(c[0]), "+f"(c[1]), "+f"(c[2]), "+f"(c[3])
        : "r"(a[0]), "r"(a[1]), "r"(a[2]), "r"(a[3]), "r"(b[0]), "r"(b[1]));
}
__device__ __forceinline__ void cp16(unsigned dst, const void* src, bool valid) {
    int sz = valid ? 16 : 0;
    asm volatile("cp.async.cg.shared.global [%0], [%1], 16, %2;"
                 :: "r"(dst), "l"(src), "r"(sz));
}
#define CP_COMMIT() asm volatile("cp.async.commit_group;")
#define CP_WAIT1()  asm volatile("cp.async.wait_group 1;")
#define CP_WAIT0()  asm volatile("cp.async.wait_group 0;")

template<int TN>
__global__ __launch_bounds__(256)
void gemm_tc_kernel(int a_sel, int K, long long w_off0, long long w_stride,
                    long long c_off0, long long c_stride, int Fout,
                    const float* __restrict__ att) {
    constexpr int TM = 128, BK = 16;
    constexpr int APITCH = 24;
    constexpr int BPITCH = TN + 8;
    constexpr int NF = TN / 32;
    constexpr int ASTAGE = TM * APITCH;
    constexpr int BSTAGE = BK * BPITCH;

    const __nv_bfloat16* Ahi = a_sel ? g_hhi : g_xhi;
    const __nv_bfloat16* Alo = a_sel ? g_hlo : g_xlo;
    long long w_off = w_off0 + (long long)blockIdx.y * w_stride;
    const __nv_bfloat16* Whi = g_whi + w_off;
    const __nv_bfloat16* Wlo = g_wlo + w_off;
    float* C = g_pool + c_off0 + (long long)blockIdx.y * c_stride;
    float* dots = blockIdx.y ? g_dr : g_dl;
    bool isL = (blockIdx.y == 0);
    __half* xh = a_sel ? g_xl2h : g_xl1h;

    extern __shared__ __align__(16) __nv_bfloat16 sm[];
    __nv_bfloat16* Ah = sm;
    __nv_bfloat16* Al = Ah + 3 * ASTAGE;
    __nv_bfloat16* Bh = Al + 3 * ASTAGE;
    __nv_bfloat16* Bl = Bh + 3 * BSTAGE;
    float* sdot = (float*)sm;          // reused after mainloop

    int t = threadIdx.x;
    int lane = t & 31, wid = t >> 5;
    int warp_m = wid & 1, warp_n = wid >> 1;
    int m_off = warp_m * 64, n_off = warp_n * (TN / 4);
    int row0 = blockIdx.x * TM;
    int N = NN;

    float c[4][NF][4];
    #pragma unroll
    for (int i = 0; i < 4; i++)
        #pragma unroll
        for (int j = 0; j < NF; j++)
            #pragma unroll
            for (int q = 0; q < 4; q++) c[i][j][q] = 0.0f;

    int g = lane >> 3, r = lane & 7;
    int a_row = (g & 1) * 8 + r;
    int a_col = (g >> 1) * 8;
    int b_krow = lane & 15;
    int b_chalf = (lane >> 4) * 8;

    int am = t >> 1;
    int ac = (t & 1) * 8;

    const int NIT = K / BK;

    auto load_stage = [&](int it, int s) {
        int k0 = it * BK;
        int grow = row0 + am;
        bool v = grow < N;
        cp16((unsigned)__cvta_generic_to_shared(Ah + s * ASTAGE + am * APITCH + ac),
             Ahi + (size_t)grow * K + k0 + ac, v);
        cp16((unsigned)__cvta_generic_to_shared(Al + s * ASTAGE + am * APITCH + ac),
             Alo + (size_t)grow * K + k0 + ac, v);
        if (TN == 128) {
            int kk = t >> 4, ch = (t & 15) * 8;
            cp16((unsigned)__cvta_generic_to_shared(Bh + s * BSTAGE + kk * BPITCH + ch),
                 Whi + (size_t)(k0 + kk) * Fout + ch, true);
            cp16((unsigned)__cvta_generic_to_shared(Bl + s * BSTAGE + kk * BPITCH + ch),
                 Wlo + (size_t)(k0 + kk) * Fout + ch, true);
        } else {
            if (t < 128) {
                int kk = t >> 3, ch = (t & 7) * 8;
                cp16((unsigned)__cvta_generic_to_shared(Bh + s * BSTAGE + kk * BPITCH + ch),
                     Whi + (size_t)(k0 + kk) * Fout + ch, true);
                cp16((unsigned)__cvta_generic_to_shared(Bl + s * BSTAGE + kk * BPITCH + ch),
                     Wlo + (size_t)(k0 + kk) * Fout + ch, true);
            }
        }
    };

    load_stage(0, 0);
    CP_COMMIT();
    if (NIT > 1) load_stage(1, 1);
    CP_COMMIT();

    for (int it = 0; it < NIT; it++) {
        CP_WAIT1();
        __syncthreads();
        if (it + 2 < NIT) load_stage(it + 2, (it + 2) % 3);
        CP_COMMIT();

        int s = it % 3;
        unsigned ah[4][4], bh[NF][2];
        #pragma unroll
        for (int i = 0; i < 4; i++)
            ldsm_x4(ah[i], (unsigned)__cvta_generic_to_shared(
                        Ah + s * ASTAGE + (m_off + i * 16 + a_row) * APITCH + a_col));
        #pragma unroll
        for (int j = 0; j < NF; j += 2)
            ldsm_x4t(&bh[j][0], (unsigned)__cvta_generic_to_shared(
                        Bh + s * BSTAGE + b_krow * BPITCH + n_off + j * 8 + b_chalf));
        #pragma unroll
        for (int i = 0; i < 4; i++)
            #pragma unroll
            for (int j = 0; j < NF; j++) mma_bf16(c[i][j], ah[i], bh[j]);

        unsigned bl[NF][2];
        #pragma unroll
        for (int j = 0; j < NF; j += 2)
            ldsm_x4t(&bl[j][0], (unsigned)__cvta_generic_to_shared(
                        Bl + s * BSTAGE + b_krow * BPITCH + n_off + j * 8 + b_chalf));
        #pragma unroll
        for (int i = 0; i < 4; i++)
            #pragma unroll
            for (int j = 0; j < NF; j++) mma_bf16(c[i][j], ah[i], bl[j]);

        unsigned al[4][4];
        #pragma unroll
        for (int i = 0; i < 4; i++)
            ldsm_x4(al[i], (unsigned)__cvta_generic_to_shared(
                        Al + s * ASTAGE + (m_off + i * 16 + a_row) * APITCH + a_col));
        #pragma unroll
        for (int i = 0; i < 4; i++)
            #pragma unroll
            for (int j = 0; j < NF; j++) mma_bf16(c[i][j], al[i], bh[j]);
    }

    // ---- epilogue: stores (fp16 xl for L, fp32 for R) + fused att-dot ----
    CP_WAIT0();
    __syncthreads();                 // all ldsm reads done; smem reusable
    if (t < TM) sdot[t] = 0.0f;
    __syncthreads();

    int lr = lane >> 2;
    int lc = (lane & 3) * 2;
    #pragma unroll
    for (int i = 0; i < 4; i++) {
        int gr = row0 + m_off + i * 16 + lr;
        float p0 = 0.0f, p1 = 0.0f;
        #pragma unroll
        for (int j = 0; j < NF; j++) {
            int gc = n_off + j * 8 + lc;
            float a0 = att[gc], a1 = att[gc + 1];
            if (gr < N) {
                if (isL)
                    *(__half2*)(xh + (size_t)gr * Fout + gc) =
                        __floats2half2_rn(c[i][j][0], c[i][j][1]);
                else
                    *(float2*)(C + (size_t)gr * Fout + gc) =
                        make_float2(c[i][j][0], c[i][j][1]);
            }
            if (gr + 8 < N) {
                if (isL)
                    *(__half2*)(xh + (size_t)(gr + 8) * Fout + gc) =
                        __floats2half2_rn(c[i][j][2], c[i][j][3]);
                else
                    *(float2*)(C + (size_t)(gr + 8) * Fout + gc) =
                        make_float2(c[i][j][2], c[i][j][3]);
            }
            p0 = fmaf(c[i][j][0], a0, fmaf(c[i][j][1], a1, p0));
            p1 = fmaf(c[i][j][2], a0, fmaf(c[i][j][3], a1, p1));
        }
        // butterfly over lane bits 0,1: lanes 4*lr..4*lr+3 hold same-row partials
        p0 += __shfl_xor_sync(0xFFFFFFFFu, p0, 1);
        p0 += __shfl_xor_sync(0xFFFFFFFFu, p0, 2);
        p1 += __shfl_xor_sync(0xFFFFFFFFu, p1, 1);
        p1 += __shfl_xor_sync(0xFFFFFFFFu, p1, 2);
        if ((lane & 3) == 0) {
            atomicAdd(&sdot[m_off + i * 16 + lr], p0);
            atomicAdd(&sdot[m_off + i * 16 + lr + 8], p1);
        }
    }
    __syncthreads();
    if (t < TM && row0 + t < N) dots[row0 + t] = sdot[t];
}

// ---------------------------------------------------------------------------
// Fused per-node kernel: warp/node, constant-shift softmax, batched 8-edge
// split-tree reduction. xl gather from fp16 (half the bytes).
// ---------------------------------------------------------------------------
template<int F, bool RELU, bool EMIT_BF16>
__global__ __launch_bounds__(256)
void node_kernel(long long xr_off,
                 const float* __restrict__ att,
                 const float* __restrict__ bias,
                 float* __restrict__ outp) {
    int node = (int)(((long long)blockIdx.x * blockDim.x + threadIdx.x) >> 5);
    int lane = threadIdx.x & 31;
    if (node >= NN) return;

    const __half* xlh = (F == 128) ? g_xl1h : g_xl2h;
    const float* xr = g_pool + xr_off;
    int s0 = g_off[node], s1 = g_off[node + 1];
    float dr = g_dr[node];
    bool h16 = (lane & 16) != 0;
    bool h8  = (lane & 8)  != 0;
    bool h4  = (lane & 4)  != 0;

    if (F == 128) {
        float4 xr4 = *(const float4*)(xr + (size_t)node * F + lane * 4);
        float4 at4 = *(const float4*)(att + lane * 4);
        float4 acc = make_float4(0.f, 0.f, 0.f, 0.f);
        float ssum = 0.0f;

        for (int base = s0; base < s1; base += 32) {
            int cnt = min(32, s1 - base);
            int safe = min(base + lane, s1 - 1);
            int sid = g_ssrc[safe];
            float pinit = 1.5f * (g_dl[sid] + dr);

            for (int bq = 0; bq < cnt; bq += 8) {
                float4 av[8];
                float p[8];
                #pragma unroll
                for (int j = 0; j < 8; j++) {
                    int sj = __shfl_sync(0xFFFFFFFFu, sid, bq + j);
                    uint2 raw = *(const uint2*)(xlh + (size_t)sj * F + lane * 4);
                    float2 f01 = __half22float2(*(__half2*)&raw.x);
                    float2 f23 = __half22float2(*(__half2*)&raw.y);
                    av[j] = make_float4(f01.x, f01.y, f23.x, f23.y);
                    float zx = av[j].x + xr4.x, zy = av[j].y + xr4.y;
                    float zz = av[j].z + xr4.z, zw = av[j].w + xr4.w;
                    p[j] = fmaf(at4.x, fabsf(zx),
                           fmaf(at4.y, fabsf(zy),
                           fmaf(at4.z, fabsf(zz), at4.w * fabsf(zw))));
                    if (lane == bq + j) p[j] += pinit;
                }
                // split-tree reduce: 9 shfl for 8 edge sums
                float q[4];
                #pragma unroll
                for (int k = 0; k < 4; k++) {
                    float sendv = h16 ? p[k] : p[k + 4];
                    float recv = __shfl_xor_sync(0xFFFFFFFFu, sendv, 16);
                    q[k] = (h16 ? p[k + 4] : p[k]) + recv;
                }
                float rr[2];
                #pragma unroll
                for (int k = 0; k < 2; k++) {
                    float sendv = h8 ? q[k] : q[k + 2];
                    float recv = __shfl_xor_sync(0xFFFFFFFFu, sendv, 8);
                    rr[k] = (h8 ? q[k + 2] : q[k]) + recv;
                }
                float sendv = h4 ? rr[0] : rr[1];
                float recv = __shfl_xor_sync(0xFFFFFFFFu, sendv, 4);
                float s = (h4 ? rr[1] : rr[0]) + recv;
                s += __shfl_xor_sync(0xFFFFFFFFu, s, 2);
                s += __shfl_xor_sync(0xFFFFFFFFu, s, 1);
                float w = __expf(fmaf(0.4f, s, -20.0f));
                #pragma unroll
                for (int j = 0; j < 8; j++) {
                    float wj = __shfl_sync(0xFFFFFFFFu, w, 4 * j);
                    wj = (bq + j < cnt) ? wj : 0.0f;
                    ssum += wj;
                    acc.x = fmaf(wj, av[j].x, acc.x);
                    acc.y = fmaf(wj, av[j].y, acc.y);
                    acc.z = fmaf(wj, av[j].z, acc.z);
                    acc.w = fmaf(wj, av[j].w, acc.w);
                }
            }
        }
        float inv = 1.0f / (ssum + 1e-16f);
        float4 bb = *(const float4*)(bias + lane * 4);
        float v0 = acc.x * inv + bb.x, v1 = acc.y * inv + bb.y;
        float v2 = acc.z * inv + bb.z, v3 = acc.w * inv + bb.w;
        if (RELU) {
            v0 = fmaxf(v0, 0.f); v1 = fmaxf(v1, 0.f);
            v2 = fmaxf(v2, 0.f); v3 = fmaxf(v3, 0.f);
        }
        if (EMIT_BF16) {
            size_t o = (size_t)node * F + lane * 4;
            __nv_bfloat16 h0 = __float2bfloat16(v0), h1 = __float2bfloat16(v1);
            __nv_bfloat16 h2 = __float2bfloat16(v2), h3 = __float2bfloat16(v3);
            *(__nv_bfloat162*)(g_hhi + o)     = __nv_bfloat162(h0, h1);
            *(__nv_bfloat162*)(g_hhi + o + 2) = __nv_bfloat162(h2, h3);
            *(__nv_bfloat162*)(g_hlo + o) = __nv_bfloat162(
                __float2bfloat16(v0 - __bfloat162float(h0)),
                __float2bfloat16(v1 - __bfloat162float(h1)));
            *(__nv_bfloat162*)(g_hlo + o + 2) = __nv_bfloat162(
                __float2bfloat16(v2 - __bfloat162float(h2)),
                __float2bfloat16(v3 - __bfloat162float(h3)));
        } else {
            *(float4*)(outp + (size_t)node * F + lane * 4) = make_float4(v0, v1, v2, v3);
        }
    } else { // F == 64
        float2 xr2 = *(const float2*)(xr + (size_t)node * F + lane * 2);
        float2 at2 = *(const float2*)(att + lane * 2);
        float2 acc = make_float2(0.f, 0.f);
        float ssum = 0.0f;

        for (int base = s0; base < s1; base += 32) {
            int cnt = min(32, s1 - base);
            int safe = min(base + lane, s1 - 1);
            int sid = g_ssrc[safe];
            float pinit = 1.5f * (g_dl[sid] + dr);

            for (int bq = 0; bq < cnt; bq += 8) {
                float2 av[8];
                float p[8];
                #pragma unroll
                for (int j = 0; j < 8; j++) {
                    int sj = __shfl_sync(0xFFFFFFFFu, sid, bq + j);
                    unsigned raw = *(const unsigned*)(xlh + (size_t)sj * F + lane * 2);
                    av[j] = __half22float2(*(__half2*)&raw);
                    float zx = av[j].x + xr2.x, zy = av[j].y + xr2.y;
                    p[j] = fmaf(at2.x, fabsf(zx), at2.y * fabsf(zy));
                    if (lane == bq + j) p[j] += pinit;
                }
                float q[4];
                #pragma unroll
                for (int k = 0; k < 4; k++) {
                    float sendv = h16 ? p[k] : p[k + 4];
                    float recv = __shfl_xor_sync(0xFFFFFFFFu, sendv, 16);
                    q[k] = (h16 ? p[k + 4] : p[k]) + recv;
                }
                float rr[2];
                #pragma unroll
                for (int k = 0; k < 2; k++) {
                    float sendv = h8 ? q[k] : q[k + 2];
                    float recv = __shfl_xor_sync(0xFFFFFFFFu, sendv, 8);
                    rr[k] = (h8 ? q[k + 2] : q[k]) + recv;
                }
                float sendv = h4 ? rr[0] : rr[1];
                float recv = __shfl_xor_sync(0xFFFFFFFFu, sendv, 4);
                float s = (h4 ? rr[1] : rr[0]) + recv;
                s += __shfl_xor_sync(0xFFFFFFFFu, s, 2);
                s += __shfl_xor_sync(0xFFFFFFFFu, s, 1);
                float w = __expf(fmaf(0.4f, s, -20.0f));
                #pragma unroll
                for (int j = 0; j < 8; j++) {
                    float wj = __shfl_sync(0xFFFFFFFFu, w, 4 * j);
                    wj = (bq + j < cnt) ? wj : 0.0f;
                    ssum += wj;
                    acc.x = fmaf(wj, av[j].x, acc.x);
                    acc.y = fmaf(wj, av[j].y, acc.y);
                }
            }
        }
        float inv = 1.0f / (ssum + 1e-16f);
        float2 bb = *(const float2*)(bias + lane * 2);
        float v0 = acc.x * inv + bb.x, v1 = acc.y * inv + bb.y;
        if (RELU) { v0 = fmaxf(v0, 0.f); v1 = fmaxf(v1, 0.f); }
        *(float2*)(outp + (size_t)node * F + lane * 2) = make_float2(v0, v1);
    }
}

// ---------------------------------------------------------------------------
// Host launch (serial main stream + CSR/convert side streams)
// ---------------------------------------------------------------------------
extern "C" void kernel_launch(void* const* d_in, const int* in_sizes, int n_in,
                              void* d_out, int out_size) {
    const float* x    = (const float*)d_in[0];
    const int*   ei   = (const int*)d_in[1];
    const float* Wl1  = (const float*)d_in[2];
    const float* Wr1  = (const float*)d_in[3];
    const float* att1 = (const float*)d_in[4];
    const float* b1   = (const float*)d_in[5];
    const float* Wl2  = (const float*)d_in[6];
    const float* Wr2  = (const float*)d_in[7];
    const float* att2 = (const float*)d_in[8];
    const float* b2   = (const float*)d_in[9];
    float* out = (float*)d_out;

    int E = in_sizes[1] / 2;
    const int* srcp = ei;
    const int* dstp = ei + E;

    constexpr int SMEM128 = (3 * 128 * 24 * 2 + 3 * 16 * (128 + 8) * 2) * 2;  // 62976 B
    constexpr int SMEM64  = (3 * 128 * 24 * 2 + 3 * 16 * (64 + 8) * 2) * 2;   // 50688 B

    static cudaStream_t s2 = nullptr, s3 = nullptr;
    static cudaEvent_t e_fork, e_w1, e_w2, e_csr;
    if (!s2) {
        cudaStreamCreateWithFlags(&s2, cudaStreamNonBlocking);
        cudaStreamCreateWithFlags(&s3, cudaStreamNonBlocking);
        cudaEventCreateWithFlags(&e_fork, cudaEventDisableTiming);
        cudaEventCreateWithFlags(&e_w1,   cudaEventDisableTiming);
        cudaEventCreateWithFlags(&e_w2,   cudaEventDisableTiming);
        cudaEventCreateWithFlags(&e_csr,  cudaEventDisableTiming);
        cudaFuncSetAttribute((const void*)gemm_tc_kernel<128>,
                             cudaFuncAttributeMaxDynamicSharedMemorySize, SMEM128);
        cudaFuncSetAttribute((const void*)gemm_tc_kernel<64>,
                             cudaFuncAttributeMaxDynamicSharedMemorySize, SMEM64);
    }

    cudaStream_t m = 0;
    int eBlocks4 = (E + 1023) / 1024;
    int warpGrid = (NN * 32 + 255) / 256;

    cudaEventRecord(e_fork, m);
    cudaStreamWaitEvent(s2, e_fork, 0);
    cudaStreamWaitEvent(s3, e_fork, 0);

    // m: x convert
    cvt_kernel<<<(int)(((long long)NN * FIN / 4 + 255) / 256), 256, 0, m>>>(
        x, 0, 0, (long long)NN * FIN);

    // s3: weight converts
    cvt_kernel<<<32, 256, 0, s3>>>(Wl1, 1, 0, 32768);
    cvt_kernel<<<32, 256, 0, s3>>>(Wr1, 1, 32768, 32768);
    cudaEventRecord(e_w1, s3);
    cvt_kernel<<<8,  256, 0, s3>>>(Wl2, 1, 65536, 8192);
    cvt_kernel<<<8,  256, 0, s3>>>(Wr2, 1, 73728, 8192);
    cudaEventRecord(e_w2, s3);

    // m: merged layer-1 GEMM (L y=0 -> fp16 xl1 + g_dl, R y=1 -> fp32 xr1 + g_dr)
    cudaStreamWaitEvent(m, e_w1, 0);
    gemm_tc_kernel<128><<<dim3((NN + 127) / 128, 2), 256, SMEM128, m>>>(
        0, FIN, 0, 32768, OFF_XL1, (long long)NN * HH, HH, att1);

    // s2: CSR build (overlaps converts + gemm1)
    zero_cnt_kernel<<<NBLK, 256, 0, s2>>>();
    hist_kernel<<<eBlocks4, 256, 0, s2>>>(dstp, E);
    scan1_kernel<<<NBLK, 256, 0, s2>>>();
    scan2_kernel<<<1, 256, 0, s2>>>();
    scan3_kernel<<<NBLK, 256, 0, s2>>>(E);
    scatter_kernel<<<eBlocks4, 256, 0, s2>>>(srcp, dstp, E);
    cudaEventRecord(e_csr, s2);

    // m: node1 (fp16 gather; emits h as bf16 hi/lo)
    cudaStreamWaitEvent(m, e_csr, 0);
    node_kernel<128, true, true><<<warpGrid, 256, 0, m>>>(
        OFF_XR1, att1, b1, nullptr);

    // m: merged layer-2 GEMM
    cudaStreamWaitEvent(m, e_w2, 0);
    gemm_tc_kernel<64><<<dim3((NN + 127) / 128, 2), 256, SMEM64, m>>>(
        1, HH, 65536, 8192, OFF_XL2, (long long)NN * CC, CC, att2);

    // m: node2 -> out (fp16 gather)
    node_kernel<64, false, false><<<warpGrid, 256, 0, m>>>(
        OFF_XR2, att2, b2, out);
}

// round 16
// speedup vs baseline: 1.1836x; 1.0147x over previous
#include <cuda_runtime.h>
#include <cuda_bf16.h>
#include <cuda_fp16.h>
#include <math.h>

// ---------------------------------------------------------------------------
// Problem constants
// ---------------------------------------------------------------------------
#define NN   50000
#define FIN  256
#define HH   128
#define CC   64
#define EMAX 1600000
#define NBLK 196              // ceil(NN/256)

// ---------------------------------------------------------------------------
// Static scratch
// ---------------------------------------------------------------------------
constexpr long long OFF_XL1 = 0;
constexpr long long OFF_XR1 = (long long)NN * HH;
constexpr long long OFF_XL2 = 2LL * NN * HH;
constexpr long long OFF_XR2 = OFF_XL2 + (long long)NN * CC;
constexpr long long POOL_SZ = OFF_XR2 + (long long)NN * CC;

__device__ float g_pool[POOL_SZ];

__device__ __nv_bfloat16 g_xhi[(long long)NN * FIN];
__device__ __nv_bfloat16 g_xlo[(long long)NN * FIN];
__device__ __nv_bfloat16 g_hhi[(long long)NN * HH];
__device__ __nv_bfloat16 g_hlo[(long long)NN * HH];
// packed weights: W1L @0 (32768), W1R @32768, W2L @65536 (8192), W2R @73728
__device__ __nv_bfloat16 g_whi[81920];
__device__ __nv_bfloat16 g_wlo[81920];

// fp16 gather operands for node kernels (xl transforms)
__device__ __half g_xl1h[(long long)NN * HH];
__device__ __half g_xl2h[(long long)NN * CC];

__device__ float g_dl[NN];
__device__ float g_dr[NN];

__device__ int g_cnt[NN];
__device__ int g_off[NN + 1];
__device__ int g_cur[NN];
__device__ int g_bsum[256];
__device__ int g_ssrc[EMAX];

// ---------------------------------------------------------------------------
// fp32 -> bf16 hi/lo conversion
// ---------------------------------------------------------------------------
__global__ void cvt_kernel(const float* __restrict__ src, int sel,
                           long long doff, long long n) {
    __nv_bfloat16* hi = sel ? g_whi : g_xhi;
    __nv_bfloat16* lo = sel ? g_wlo : g_xlo;
    long long i = ((long long)blockIdx.x * blockDim.x + threadIdx.x) * 4;
    if (i >= n) return;
    float4 v = *(const float4*)(src + i);
    float vv[4] = {v.x, v.y, v.z, v.w};
    __nv_bfloat16 h[4], l[4];
    #pragma unroll
    for (int j = 0; j < 4; j++) {
        h[j] = __float2bfloat16(vv[j]);
        l[j] = __float2bfloat16(vv[j] - __bfloat162float(h[j]));
    }
    *(__nv_bfloat162*)(hi + doff + i)     = __nv_bfloat162(h[0], h[1]);
    *(__nv_bfloat162*)(hi + doff + i + 2) = __nv_bfloat162(h[2], h[3]);
    *(__nv_bfloat162*)(lo + doff + i)     = __nv_bfloat162(l[0], l[1]);
    *(__nv_bfloat162*)(lo + doff + i + 2) = __nv_bfloat162(l[2], l[3]);
}

// ---------------------------------------------------------------------------
// CSR construction
// ---------------------------------------------------------------------------
__global__ void zero_cnt_kernel() {
    int i = blockIdx.x * blockDim.x + threadIdx.x;
    if (i < NN) g_cnt[i] = 0;
}

__global__ void hist_kernel(const int* __restrict__ dst, int E) {
    int i0 = (blockIdx.x * blockDim.x + threadIdx.x) * 4;
    #pragma unroll
    for (int j = 0; j < 4; j++) {
        int i = i0 + j;
        if (i < E) atomicAdd(&g_cnt[dst[i]], 1);
    }
}

__global__ void scan1_kernel() {
    __shared__ int wt[8];
    int t = threadIdx.x, lane = t & 31, wid = t >> 5;
    int idx = blockIdx.x * 256 + t;
    int v = (idx < NN) ? g_cnt[idx] : 0;
    int x = v;
    #pragma unroll
    for (int o = 1; o < 32; o <<= 1) {
        int tmp = __shfl_up_sync(0xFFFFFFFFu, x, o);
        if (lane >= o) x += tmp;
    }
    if (lane == 31) wt[wid] = x;
    __syncthreads();
    if (wid == 0 && lane < 8) {
        int w = wt[lane], wx = w;
        #pragma unroll
        for (int o = 1; o < 8; o <<= 1) {
            int tmp = __shfl_up_sync(0xFFu, wx, o);
            if (lane >= o) wx += tmp;
        }
        wt[lane] = wx - w;
    }
    __syncthreads();
    int excl = x - v + wt[wid];
    if (idx < NN) g_off[idx] = excl;
    if (t == 255) g_bsum[blockIdx.x] = excl + v;
}

__global__ void scan2_kernel() {
    __shared__ int wt[8];
    int t = threadIdx.x, lane = t & 31, wid = t >> 5;
    int v = (t < NBLK) ? g_bsum[t] : 0;
    int x = v;
    #pragma unroll
    for (int o = 1; o < 32; o <<= 1) {
        int tmp = __shfl_up_sync(0xFFFFFFFFu, x, o);
        if (lane >= o) x += tmp;
    }
    if (lane == 31) wt[wid] = x;
    __syncthreads();
    if (wid == 0 && lane < 8) {
        int w = wt[lane], wx = w;
        #pragma unroll
        for (int o = 1; o < 8; o <<= 1) {
            int tmp = __shfl_up_sync(0xFFu, wx, o);
            if (lane >= o) wx += tmp;
        }
        wt[lane] = wx - w;
    }
    __syncthreads();
    if (t < NBLK) g_bsum[t] = x - v + wt[wid];
}

__global__ void scan3_kernel(int E) {
    int idx = blockIdx.x * 256 + threadIdx.x;
    if (idx < NN) {
        int o = g_off[idx] + g_bsum[blockIdx.x];
        g_off[idx] = o;
        g_cur[idx] = o;
    }
    if (idx == 0) g_off[NN] = E;
}

__global__ void scatter_kernel(const int* __restrict__ src,
                               const int* __restrict__ dst, int E) {
    int i0 = (blockIdx.x * blockDim.x + threadIdx.x) * 4;
    #pragma unroll
    for (int j = 0; j < 4; j++) {
        int i = i0 + j;
        if (i < E) {
            int pos = atomicAdd(&g_cur[dst[i]], 1);
            g_ssrc[pos] = src[i];
        }
    }
}

// ---------------------------------------------------------------------------
// Tensor-core GEMM, bf16 hi/lo, 3-stage cp.async pipeline, merged L/R via
// blockIdx.y, fused att-dot epilogue (-> g_dl y=0, g_dr y=1).
// y==0 (L operand) emits fp16 xl instead of fp32 C (node kernels gather fp16).
// Epilogue dot: butterfly pre-reduction + atomic-free [row][warp_n] staging.
// ---------------------------------------------------------------------------
__device__ __forceinline__ void ldsm_x4(unsigned* r, unsigned addr) {
    asm volatile("ldmatrix.sync.aligned.m8n8.x4.shared.b16 {%0,%1,%2,%3}, [%4];"
                 : "=r"(r[0]), "=r"(r[1]), "=r"(r[2]), "=r"(r[3]) : "r"(addr));
}
__device__ __forceinline__ void ldsm_x4t(unsigned* r, unsigned addr) {
    asm volatile("ldmatrix.sync.aligned.m8n8.x4.trans.shared.b16 {%0,%1,%2,%3}, [%4];"
                 : "=r"(r[0]), "=r"(r[1]), "=r"(r[2]), "=r"(r[3]) : "r"(addr));
}
__device__ __forceinline__ void mma_bf16(float* c, const unsigned* a, const unsigned* b) {
    asm volatile(
        "mma.sync.aligned.m16n8k16.row.col.f32.bf16.bf16.f32 "
        "{%0,%1,%2,%3}, {%4,%5,%6,%7}, {%8,%9}, {%0,%1,%2,%3};"
        : "+f"(c[0]), "+f"(c[1]), "+f"(c[2]), "+f"(c[3])
        : "r"(a[0]), "r"(a[1]), "r"(a[2]), "r"(a[3]), "r"(b[0]), "r"(b[1]));
}
__device__ __forceinline__ void cp16(unsigned dst, const void* src, bool valid) {
    int sz = valid ? 16 : 0;
    asm volatile("cp.async.cg.shared.global [%0], [%1], 16, %2;"
                 :: "r"(dst), "l"(src), "r"(sz));
}
#define CP_COMMIT() asm volatile("cp.async.commit_group;")
#define CP_WAIT1()  asm volatile("cp.async.wait_group 1;")
#define CP_WAIT0()  asm volatile("cp.async.wait_group 0;")

template<int TN>
__global__ __launch_bounds__(256)
void gemm_tc_kernel(int a_sel, int K, long long w_off0, long long w_stride,
                    long long c_off0, long long c_stride, int Fout,
                    const float* __restrict__ att) {
    constexpr int TM = 128, BK = 16;
    constexpr int APITCH = 24;
    constexpr int BPITCH = TN + 8;
    constexpr int NF = TN / 32;
    constexpr int ASTAGE = TM * APITCH;
    constexpr int BSTAGE = BK * BPITCH;

    const __nv_bfloat16* Ahi = a_sel ? g_hhi : g_xhi;
    const __nv_bfloat16* Alo = a_sel ? g_hlo : g_xlo;
    long long w_off = w_off0 + (long long)blockIdx.y * w_stride;
    const __nv_bfloat16* Whi = g_whi + w_off;
    const __nv_bfloat16* Wlo = g_wlo + w_off;
    float* C = g_pool + c_off0 + (long long)blockIdx.y * c_stride;
    float* dots = blockIdx.y ? g_dr : g_dl;
    bool isL = (blockIdx.y == 0);
    __half* xh = a_sel ? g_xl2h : g_xl1h;

    extern __shared__ __align__(16) __nv_bfloat16 sm[];
    __nv_bfloat16* Ah = sm;
    __nv_bfloat16* Al = Ah + 3 * ASTAGE;
    __nv_bfloat16* Bh = Al + 3 * ASTAGE;
    __nv_bfloat16* Bl = Bh + 3 * BSTAGE;
    float* sdot = (float*)sm;          // reused after mainloop: [TM][4]

    int t = threadIdx.x;
    int lane = t & 31, wid = t >> 5;
    int warp_m = wid & 1, warp_n = wid >> 1;
    int m_off = warp_m * 64, n_off = warp_n * (TN / 4);
    int row0 = blockIdx.x * TM;
    int N = NN;

    float c[4][NF][4];
    #pragma unroll
    for (int i = 0; i < 4; i++)
        #pragma unroll
        for (int j = 0; j < NF; j++)
            #pragma unroll
            for (int q = 0; q < 4; q++) c[i][j][q] = 0.0f;

    int g = lane >> 3, r = lane & 7;
    int a_row = (g & 1) * 8 + r;
    int a_col = (g >> 1) * 8;
    int b_krow = lane & 15;
    int b_chalf = (lane >> 4) * 8;

    int am = t >> 1;
    int ac = (t & 1) * 8;

    const int NIT = K / BK;

    auto load_stage = [&](int it, int s) {
        int k0 = it * BK;
        int grow = row0 + am;
        bool v = grow < N;
        cp16((unsigned)__cvta_generic_to_shared(Ah + s * ASTAGE + am * APITCH + ac),
             Ahi + (size_t)grow * K + k0 + ac, v);
        cp16((unsigned)__cvta_generic_to_shared(Al + s * ASTAGE + am * APITCH + ac),
             Alo + (size_t)grow * K + k0 + ac, v);
        if (TN == 128) {
            int kk = t >> 4, ch = (t & 15) * 8;
            cp16((unsigned)__cvta_generic_to_shared(Bh + s * BSTAGE + kk * BPITCH + ch),
                 Whi + (size_t)(k0 + kk) * Fout + ch, true);
            cp16((unsigned)__cvta_generic_to_shared(Bl + s * BSTAGE + kk * BPITCH + ch),
                 Wlo + (size_t)(k0 + kk) * Fout + ch, true);
        } else {
            if (t < 128) {
                int kk = t >> 3, ch = (t & 7) * 8;
                cp16((unsigned)__cvta_generic_to_shared(Bh + s * BSTAGE + kk * BPITCH + ch),
                     Whi + (size_t)(k0 + kk) * Fout + ch, true);
                cp16((unsigned)__cvta_generic_to_shared(Bl + s * BSTAGE + kk * BPITCH + ch),
                     Wlo + (size_t)(k0 + kk) * Fout + ch, true);
            }
        }
    };

    load_stage(0, 0);
    CP_COMMIT();
    if (NIT > 1) load_stage(1, 1);
    CP_COMMIT();

    for (int it = 0; it < NIT; it++) {
        CP_WAIT1();
        __syncthreads();
        if (it + 2 < NIT) load_stage(it + 2, (it + 2) % 3);
        CP_COMMIT();

        int s = it % 3;
        unsigned ah[4][4], bh[NF][2];
        #pragma unroll
        for (int i = 0; i < 4; i++)
            ldsm_x4(ah[i], (unsigned)__cvta_generic_to_shared(
                        Ah + s * ASTAGE + (m_off + i * 16 + a_row) * APITCH + a_col));
        #pragma unroll
        for (int j = 0; j < NF; j += 2)
            ldsm_x4t(&bh[j][0], (unsigned)__cvta_generic_to_shared(
                        Bh + s * BSTAGE + b_krow * BPITCH + n_off + j * 8 + b_chalf));
        #pragma unroll
        for (int i = 0; i < 4; i++)
            #pragma unroll
            for (int j = 0; j < NF; j++) mma_bf16(c[i][j], ah[i], bh[j]);

        unsigned bl[NF][2];
        #pragma unroll
        for (int j = 0; j < NF; j += 2)
            ldsm_x4t(&bl[j][0], (unsigned)__cvta_generic_to_shared(
                        Bl + s * BSTAGE + b_krow * BPITCH + n_off + j * 8 + b_chalf));
        #pragma unroll
        for (int i = 0; i < 4; i++)
            #pragma unroll
            for (int j = 0; j < NF; j++) mma_bf16(c[i][j], ah[i], bl[j]);

        unsigned al[4][4];
        #pragma unroll
        for (int i = 0; i < 4; i++)
            ldsm_x4(al[i], (unsigned)__cvta_generic_to_shared(
                        Al + s * ASTAGE + (m_off + i * 16 + a_row) * APITCH + a_col));
        #pragma unroll
        for (int i = 0; i < 4; i++)
            #pragma unroll
            for (int j = 0; j < NF; j++) mma_bf16(c[i][j], al[i], bh[j]);
    }

    // ---- epilogue: stores (fp16 xl for L, fp32 for R) + fused att-dot ----
    CP_WAIT0();
    __syncthreads();                 // all ldsm reads done; smem reusable

    int lr = lane >> 2;
    int lc = (lane & 3) * 2;
    #pragma unroll
    for (int i = 0; i < 4; i++) {
        int gr = row0 + m_off + i * 16 + lr;
        float p0 = 0.0f, p1 = 0.0f;
        #pragma unroll
        for (int j = 0; j < NF; j++) {
            int gc = n_off + j * 8 + lc;
            float a0 = att[gc], a1 = att[gc + 1];
            if (gr < N) {
                if (isL)
                    *(__half2*)(xh + (size_t)gr * Fout + gc) =
                        __floats2half2_rn(c[i][j][0], c[i][j][1]);
                else
                    *(float2*)(C + (size_t)gr * Fout + gc) =
                        make_float2(c[i][j][0], c[i][j][1]);
            }
            if (gr + 8 < N) {
                if (isL)
                    *(__half2*)(xh + (size_t)(gr + 8) * Fout + gc) =
                        __floats2half2_rn(c[i][j][2], c[i][j][3]);
                else
                    *(float2*)(C + (size_t)(gr + 8) * Fout + gc) =
                        make_float2(c[i][j][2], c[i][j][3]);
            }
            p0 = fmaf(c[i][j][0], a0, fmaf(c[i][j][1], a1, p0));
            p1 = fmaf(c[i][j][2], a0, fmaf(c[i][j][3], a1, p1));
        }
        // butterfly over lane bits 0,1: lanes 4*lr..4*lr+3 hold same-row partials
        p0 += __shfl_xor_sync(0xFFFFFFFFu, p0, 1);
        p0 += __shfl_xor_sync(0xFFFFFFFFu, p0, 2);
        p1 += __shfl_xor_sync(0xFFFFFFFFu, p1, 1);
        p1 += __shfl_xor_sync(0xFFFFFFFFu, p1, 2);
        if ((lane & 3) == 0) {
            // atomic-free staging: each [row][warp_n] slot written exactly once
            sdot[(m_off + i * 16 + lr) * 4 + warp_n]     = p0;
            sdot[(m_off + i * 16 + lr + 8) * 4 + warp_n] = p1;
        }
    }
    __syncthreads();
    if (t < TM && row0 + t < N)
        dots[row0 + t] = sdot[t * 4] + sdot[t * 4 + 1]
                       + sdot[t * 4 + 2] + sdot[t * 4 + 3];
}

// ---------------------------------------------------------------------------
// Fused per-node kernel: warp/node, constant-shift softmax, batched 8-edge
// split-tree reduction. xl gather from fp16. pinit added post-reduction via
// one variable-lane shfl (no per-edge predicated adds).
// ---------------------------------------------------------------------------
template<int F, bool RELU, bool EMIT_BF16>
__global__ __launch_bounds__(256)
void node_kernel(long long xr_off,
                 const float* __restrict__ att,
                 const float* __restrict__ bias,
                 float* __restrict__ outp) {
    int node = (int)(((long long)blockIdx.x * blockDim.x + threadIdx.x) >> 5);
    int lane = threadIdx.x & 31;
    if (node >= NN) return;

    const __half* xlh = (F == 128) ? g_xl1h : g_xl2h;
    const float* xr = g_pool + xr_off;
    int s0 = g_off[node], s1 = g_off[node + 1];
    float dr = g_dr[node];
    bool h16 = (lane & 16) != 0;
    bool h8  = (lane & 8)  != 0;
    bool h4  = (lane & 4)  != 0;
    int psrc = lane >> 2;        // edge-within-batch this lane's s represents

    if (F == 128) {
        float4 xr4 = *(const float4*)(xr + (size_t)node * F + lane * 4);
        float4 at4 = *(const float4*)(att + lane * 4);
        float4 acc = make_float4(0.f, 0.f, 0.f, 0.f);
        float ssum = 0.0f;

        for (int base = s0; base < s1; base += 32) {
            int cnt = min(32, s1 - base);
            int safe = min(base + lane, s1 - 1);
            int sid = g_ssrc[safe];
            float pinit = 1.5f * (g_dl[sid] + dr);

            for (int bq = 0; bq < cnt; bq += 8) {
                float4 av[8];
                float p[8];
                #pragma unroll
                for (int j = 0; j < 8; j++) {
                    int sj = __shfl_sync(0xFFFFFFFFu, sid, bq + j);
                    uint2 raw = *(const uint2*)(xlh + (size_t)sj * F + lane * 4);
                    float2 f01 = __half22float2(*(__half2*)&raw.x);
                    float2 f23 = __half22float2(*(__half2*)&raw.y);
                    av[j] = make_float4(f01.x, f01.y, f23.x, f23.y);
                    float zx = av[j].x + xr4.x, zy = av[j].y + xr4.y;
                    float zz = av[j].z + xr4.z, zw = av[j].w + xr4.w;
                    p[j] = fmaf(at4.x, fabsf(zx),
                           fmaf(at4.y, fabsf(zy),
                           fmaf(at4.z, fabsf(zz), at4.w * fabsf(zw))));
                }
                // split-tree reduce: 9 shfl for 8 edge sums
                float q[4];
                #pragma unroll
                for (int k = 0; k < 4; k++) {
                    float sendv = h16 ? p[k] : p[k + 4];
                    float recv = __shfl_xor_sync(0xFFFFFFFFu, sendv, 16);
                    q[k] = (h16 ? p[k + 4] : p[k]) + recv;
                }
                float rr[2];
                #pragma unroll
                for (int k = 0; k < 2; k++) {
                    float sendv = h8 ? q[k] : q[k + 2];
                    float recv = __shfl_xor_sync(0xFFFFFFFFu, sendv, 8);
                    rr[k] = (h8 ? q[k + 2] : q[k]) + recv;
                }
                float sendv = h4 ? rr[0] : rr[1];
                float recv = __shfl_xor_sync(0xFFFFFFFFu, sendv, 4);
                float s = (h4 ? rr[1] : rr[0]) + recv;
                s += __shfl_xor_sync(0xFFFFFFFFu, s, 2);
                s += __shfl_xor_sync(0xFFFFFFFFu, s, 1);
                // lane 4j holds edge bq+j's abs-sum; add its pinit via one shfl
                s += __shfl_sync(0xFFFFFFFFu, pinit, bq + psrc);
                float w = __expf(fmaf(0.4f, s, -20.0f));
                #pragma unroll
                for (int j = 0; j < 8; j++) {
                    float wj = __shfl_sync(0xFFFFFFFFu, w, 4 * j);
                    wj = (bq + j < cnt) ? wj : 0.0f;
                    ssum += wj;
                    acc.x = fmaf(wj, av[j].x, acc.x);
                    acc.y = fmaf(wj, av[j].y, acc.y);
                    acc.z = fmaf(wj, av[j].z, acc.z);
                    acc.w = fmaf(wj, av[j].w, acc.w);
                }
            }
        }
        float inv = 1.0f / (ssum + 1e-16f);
        float4 bb = *(const float4*)(bias + lane * 4);
        float v0 = acc.x * inv + bb.x, v1 = acc.y * inv + bb.y;
        float v2 = acc.z * inv + bb.z, v3 = acc.w * inv + bb.w;
        if (RELU) {
            v0 = fmaxf(v0, 0.f); v1 = fmaxf(v1, 0.f);
            v2 = fmaxf(v2, 0.f); v3 = fmaxf(v3, 0.f);
        }
        if (EMIT_BF16) {
            size_t o = (size_t)node * F + lane * 4;
            __nv_bfloat16 h0 = __float2bfloat16(v0), h1 = __float2bfloat16(v1);
            __nv_bfloat16 h2 = __float2bfloat16(v2), h3 = __float2bfloat16(v3);
            *(__nv_bfloat162*)(g_hhi + o)     = __nv_bfloat162(h0, h1);
            *(__nv_bfloat162*)(g_hhi + o + 2) = __nv_bfloat162(h2, h3);
            *(__nv_bfloat162*)(g_hlo + o) = __nv_bfloat162(
                __float2bfloat16(v0 - __bfloat162float(h0)),
                __float2bfloat16(v1 - __bfloat162float(h1)));
            *(__nv_bfloat162*)(g_hlo + o + 2) = __nv_bfloat162(
                __float2bfloat16(v2 - __bfloat162float(h2)),
                __float2bfloat16(v3 - __bfloat162float(h3)));
        } else {
            *(float4*)(outp + (size_t)node * F + lane * 4) = make_float4(v0, v1, v2, v3);
        }
    } else { // F == 64
        float2 xr2 = *(const float2*)(xr + (size_t)node * F + lane * 2);
        float2 at2 = *(const float2*)(att + lane * 2);
        float2 acc = make_float2(0.f, 0.f);
        float ssum = 0.0f;

        for (int base = s0; base < s1; base += 32) {
            int cnt = min(32, s1 - base);
            int safe = min(base + lane, s1 - 1);
            int sid = g_ssrc[safe];
            float pinit = 1.5f * (g_dl[sid] + dr);

            for (int bq = 0; bq < cnt; bq += 8) {
                float2 av[8];
                float p[8];
                #pragma unroll
                for (int j = 0; j < 8; j++) {
                    int sj = __shfl_sync(0xFFFFFFFFu, sid, bq + j);
                    unsigned raw = *(const unsigned*)(xlh + (size_t)sj * F + lane * 2);
                    av[j] = __half22float2(*(__half2*)&raw);
                    float zx = av[j].x + xr2.x, zy = av[j].y + xr2.y;
                    p[j] = fmaf(at2.x, fabsf(zx), at2.y * fabsf(zy));
                }
                float q[4];
                #pragma unroll
                for (int k = 0; k < 4; k++) {
                    float sendv = h16 ? p[k] : p[k + 4];
                    float recv = __shfl_xor_sync(0xFFFFFFFFu, sendv, 16);
                    q[k] = (h16 ? p[k + 4] : p[k]) + recv;
                }
                float rr[2];
                #pragma unroll
                for (int k = 0; k < 2; k++) {
                    float sendv = h8 ? q[k] : q[k + 2];
                    float recv = __shfl_xor_sync(0xFFFFFFFFu, sendv, 8);
                    rr[k] = (h8 ? q[k + 2] : q[k]) + recv;
                }
                float sendv = h4 ? rr[0] : rr[1];
                float recv = __shfl_xor_sync(0xFFFFFFFFu, sendv, 4);
                float s = (h4 ? rr[1] : rr[0]) + recv;
                s += __shfl_xor_sync(0xFFFFFFFFu, s, 2);
                s += __shfl_xor_sync(0xFFFFFFFFu, s, 1);
                s += __shfl_sync(0xFFFFFFFFu, pinit, bq + psrc);
                float w = __expf(fmaf(0.4f, s, -20.0f));
                #pragma unroll
                for (int j = 0; j < 8; j++) {
                    float wj = __shfl_sync(0xFFFFFFFFu, w, 4 * j);
                    wj = (bq + j < cnt) ? wj : 0.0f;
                    ssum += wj;
                    acc.x = fmaf(wj, av[j].x, acc.x);
                    acc.y = fmaf(wj, av[j].y, acc.y);
                }
            }
        }
        float inv = 1.0f / (ssum + 1e-16f);
        float2 bb = *(const float2*)(bias + lane * 2);
        float v0 = acc.x * inv + bb.x, v1 = acc.y * inv + bb.y;
        if (RELU) { v0 = fmaxf(v0, 0.f); v1 = fmaxf(v1, 0.f); }
        *(float2*)(outp + (size_t)node * F + lane * 2) = make_float2(v0, v1);
    }
}

// ---------------------------------------------------------------------------
// Host launch (serial main stream + CSR/convert side streams)
// ---------------------------------------------------------------------------
extern "C" void kernel_launch(void* const* d_in, const int* in_sizes, int n_in,
                              void* d_out, int out_size) {
    const float* x    = (const float*)d_in[0];
    const int*   ei   = (const int*)d_in[1];
    const float* Wl1  = (const float*)d_in[2];
    const float* Wr1  = (const float*)d_in[3];
    const float* att1 = (const float*)d_in[4];
    const float* b1   = (const float*)d_in[5];
    const float* Wl2  = (const float*)d_in[6];
    const float* Wr2  = (const float*)d_in[7];
    const float* att2 = (const float*)d_in[8];
    const float* b2   = (const float*)d_in[9];
    float* out = (float*)d_out;

    int E = in_sizes[1] / 2;
    const int* srcp = ei;
    const int* dstp = ei + E;

    constexpr int SMEM128 = (3 * 128 * 24 * 2 + 3 * 16 * (128 + 8) * 2) * 2;  // 62976 B
    constexpr int SMEM64  = (3 * 128 * 24 * 2 + 3 * 16 * (64 + 8) * 2) * 2;   // 50688 B

    static cudaStream_t s2 = nullptr, s3 = nullptr;
    static cudaEvent_t e_fork, e_w1, e_w2, e_csr;
    if (!s2) {
        cudaStreamCreateWithFlags(&s2, cudaStreamNonBlocking);
        cudaStreamCreateWithFlags(&s3, cudaStreamNonBlocking);
        cudaEventCreateWithFlags(&e_fork, cudaEventDisableTiming);
        cudaEventCreateWithFlags(&e_w1,   cudaEventDisableTiming);
        cudaEventCreateWithFlags(&e_w2,   cudaEventDisableTiming);
        cudaEventCreateWithFlags(&e_csr,  cudaEventDisableTiming);
        cudaFuncSetAttribute((const void*)gemm_tc_kernel<128>,
                             cudaFuncAttributeMaxDynamicSharedMemorySize, SMEM128);
        cudaFuncSetAttribute((const void*)gemm_tc_kernel<64>,
                             cudaFuncAttributeMaxDynamicSharedMemorySize, SMEM64);
    }

    cudaStream_t m = 0;
    int eBlocks4 = (E + 1023) / 1024;
    int warpGrid = (NN * 32 + 255) / 256;

    cudaEventRecord(e_fork, m);
    cudaStreamWaitEvent(s2, e_fork, 0);
    cudaStreamWaitEvent(s3, e_fork, 0);

    // m: x convert
    cvt_kernel<<<(int)(((long long)NN * FIN / 4 + 255) / 256), 256, 0, m>>>(
        x, 0, 0, (long long)NN * FIN);

    // s3: weight converts
    cvt_kernel<<<32, 256, 0, s3>>>(Wl1, 1, 0, 32768);
    cvt_kernel<<<32, 256, 0, s3>>>(Wr1, 1, 32768, 32768);
    cudaEventRecord(e_w1, s3);
    cvt_kernel<<<8,  256, 0, s3>>>(Wl2, 1, 65536, 8192);
    cvt_kernel<<<8,  256, 0, s3>>>(Wr2, 1, 73728, 8192);
    cudaEventRecord(e_w2, s3);

    // m: merged layer-1 GEMM (L y=0 -> fp16 xl1 + g_dl, R y=1 -> fp32 xr1 + g_dr)
    cudaStreamWaitEvent(m, e_w1, 0);
    gemm_tc_kernel<128><<<dim3((NN + 127) / 128, 2), 256, SMEM128, m>>>(
        0, FIN, 0, 32768, OFF_XL1, (long long)NN * HH, HH, att1);

    // s2: CSR build (overlaps converts + gemm1)
    zero_cnt_kernel<<<NBLK, 256, 0, s2>>>();
    hist_kernel<<<eBlocks4, 256, 0, s2>>>(dstp, E);
    scan1_kernel<<<NBLK, 256, 0, s2>>>();
    scan2_kernel<<<1, 256, 0, s2>>>();
    scan3_kernel<<<NBLK, 256, 0, s2>>>(E);
    scatter_kernel<<<eBlocks4, 256, 0, s2>>>(srcp, dstp, E);
    cudaEventRecord(e_csr, s2);

    // m: node1 (fp16 gather; emits h as bf16 hi/lo)
    cudaStreamWaitEvent(m, e_csr, 0);
    node_kernel<128, true, true><<<warpGrid, 256, 0, m>>>(
        OFF_XR1, att1, b1, nullptr);

    // m: merged layer-2 GEMM
    cudaStreamWaitEvent(m, e_w2, 0);
    gemm_tc_kernel<64><<<dim3((NN + 127) / 128, 2), 256, SMEM64, m>>>(
        1, HH, 65536, 8192, OFF_XL2, (long long)NN * CC, CC, att2);

    // m: node2 -> out (fp16 gather)
    node_kernel<64, false, false><<<warpGrid, 256, 0, m>>>(
        OFF_XR2, att2, b2, out);
}

// round 17
// speedup vs baseline: 1.2297x; 1.0389x over previous
#include <cuda_runtime.h>
#include <cuda_bf16.h>
#include <cuda_fp16.h>
#include <math.h>

// ---------------------------------------------------------------------------
// Problem constants
// ---------------------------------------------------------------------------
#define NN   50000
#define FIN  256
#define HH   128
#define CC   64
#define EMAX 1600000
#define NBLK 196              // ceil(NN/256)

// ---------------------------------------------------------------------------
// Static scratch
// ---------------------------------------------------------------------------
constexpr long long OFF_XL1 = 0;
constexpr long long OFF_XR1 = (long long)NN * HH;
constexpr long long OFF_XL2 = 2LL * NN * HH;
constexpr long long OFF_XR2 = OFF_XL2 + (long long)NN * CC;
constexpr long long POOL_SZ = OFF_XR2 + (long long)NN * CC;

__device__ float g_pool[POOL_SZ];

__device__ __nv_bfloat16 g_xhi[(long long)NN * FIN];
__device__ __nv_bfloat16 g_xlo[(long long)NN * FIN];
__device__ __nv_bfloat16 g_hhi[(long long)NN * HH];
__device__ __nv_bfloat16 g_hlo[(long long)NN * HH];
// packed weights: W1L @0 (32768), W1R @32768, W2L @65536 (8192), W2R @73728
__device__ __nv_bfloat16 g_whi[81920];
__device__ __nv_bfloat16 g_wlo[81920];

// fp16 gather operands for node kernels (xl transforms)
__device__ __half g_xl1h[(long long)NN * HH];
__device__ __half g_xl2h[(long long)NN * CC];

__device__ float g_dl[NN];
__device__ float g_dr[NN];

__device__ int g_cnt[NN];
__device__ int g_off[NN + 1];
__device__ int g_cur[NN];
__device__ int g_bsum[256];
__device__ int g_ssrc[EMAX];

// ---------------------------------------------------------------------------
// fp32 -> bf16 hi/lo conversion
// ---------------------------------------------------------------------------
__global__ void cvt_kernel(const float* __restrict__ src, int sel,
                           long long doff, long long n) {
    __nv_bfloat16* hi = sel ? g_whi : g_xhi;
    __nv_bfloat16* lo = sel ? g_wlo : g_xlo;
    long long i = ((long long)blockIdx.x * blockDim.x + threadIdx.x) * 4;
    if (i >= n) return;
    float4 v = *(const float4*)(src + i);
    float vv[4] = {v.x, v.y, v.z, v.w};
    __nv_bfloat16 h[4], l[4];
    #pragma unroll
    for (int j = 0; j < 4; j++) {
        h[j] = __float2bfloat16(vv[j]);
        l[j] = __float2bfloat16(vv[j] - __bfloat162float(h[j]));
    }
    *(__nv_bfloat162*)(hi + doff + i)     = __nv_bfloat162(h[0], h[1]);
    *(__nv_bfloat162*)(hi + doff + i + 2) = __nv_bfloat162(h[2], h[3]);
    *(__nv_bfloat162*)(lo + doff + i)     = __nv_bfloat162(l[0], l[1]);
    *(__nv_bfloat162*)(lo + doff + i + 2) = __nv_bfloat162(l[2], l[3]);
}

// ---------------------------------------------------------------------------
// CSR construction
// ---------------------------------------------------------------------------
__global__ void zero_cnt_kernel() {
    int i = blockIdx.x * blockDim.x + threadIdx.x;
    if (i < NN) g_cnt[i] = 0;
}

__global__ void hist_kernel(const int* __restrict__ dst, int E) {
    int i0 = (blockIdx.x * blockDim.x + threadIdx.x) * 4;
    #pragma unroll
    for (int j = 0; j < 4; j++) {
        int i = i0 + j;
        if (i < E) atomicAdd(&g_cnt[dst[i]], 1);
    }
}

__global__ void scan1_kernel() {
    __shared__ int wt[8];
    int t = threadIdx.x, lane = t & 31, wid = t >> 5;
    int idx = blockIdx.x * 256 + t;
    int v = (idx < NN) ? g_cnt[idx] : 0;
    int x = v;
    #pragma unroll
    for (int o = 1; o < 32; o <<= 1) {
        int tmp = __shfl_up_sync(0xFFFFFFFFu, x, o);
        if (lane >= o) x += tmp;
    }
    if (lane == 31) wt[wid] = x;
    __syncthreads();
    if (wid == 0 && lane < 8) {
        int w = wt[lane], wx = w;
        #pragma unroll
        for (int o = 1; o < 8; o <<= 1) {
            int tmp = __shfl_up_sync(0xFFu, wx, o);
            if (lane >= o) wx += tmp;
        }
        wt[lane] = wx - w;
    }
    __syncthreads();
    int excl = x - v + wt[wid];
    if (idx < NN) g_off[idx] = excl;
    if (t == 255) g_bsum[blockIdx.x] = excl + v;
}

__global__ void scan2_kernel() {
    __shared__ int wt[8];
    int t = threadIdx.x, lane = t & 31, wid = t >> 5;
    int v = (t < NBLK) ? g_bsum[t] : 0;
    int x = v;
    #pragma unroll
    for (int o = 1; o < 32; o <<= 1) {
        int tmp = __shfl_up_sync(0xFFFFFFFFu, x, o);
        if (lane >= o) x += tmp;
    }
    if (lane == 31) wt[wid] = x;
    __syncthreads();
    if (wid == 0 && lane < 8) {
        int w = wt[lane], wx = w;
        #pragma unroll
        for (int o = 1; o < 8; o <<= 1) {
            int tmp = __shfl_up_sync(0xFFu, wx, o);
            if (lane >= o) wx += tmp;
        }
        wt[lane] = wx - w;
    }
    __syncthreads();
    if (t < NBLK) g_bsum[t] = x - v + wt[wid];
}

__global__ void scan3_kernel(int E) {
    int idx = blockIdx.x * 256 + threadIdx.x;
    if (idx < NN) {
        int o = g_off[idx] + g_bsum[blockIdx.x];
        g_off[idx] = o;
        g_cur[idx] = o;
    }
    if (idx == 0) g_off[NN] = E;
}

__global__ void scatter_kernel(const int* __restrict__ src,
                               const int* __restrict__ dst, int E) {
    int i0 = (blockIdx.x * blockDim.x + threadIdx.x) * 4;
    #pragma unroll
    for (int j = 0; j < 4; j++) {
        int i = i0 + j;
        if (i < E) {
            int pos = atomicAdd(&g_cur[dst[i]], 1);
            g_ssrc[pos] = src[i];
        }
    }
}

// ---------------------------------------------------------------------------
// Tensor-core GEMM, bf16 hi/lo, 3-stage cp.async pipeline, merged L/R via
// blockIdx.y, fused att-dot epilogue (-> g_dl y=0, g_dr y=1).
// y==0 (L operand) emits fp16 xl instead of fp32 C (node kernels gather fp16).
// Epilogue dot: butterfly pre-reduction + atomic-free [row][warp_n] staging.
// ---------------------------------------------------------------------------
__device__ __forceinline__ void ldsm_x4(unsigned* r, unsigned addr) {
    asm volatile("ldmatrix.sync.aligned.m8n8.x4.shared.b16 {%0,%1,%2,%3}, [%4];"
                 : "=r"(r[0]), "=r"(r[1]), "=r"(r[2]), "=r"(r[3]) : "r"(addr));
}
__device__ __forceinline__ void ldsm_x4t(unsigned* r, unsigned addr) {
    asm volatile("ldmatrix.sync.aligned.m8n8.x4.trans.shared.b16 {%0,%1,%2,%3}, [%4];"
                 : "=r"(r[0]), "=r"(r[1]), "=r"(r[2]), "=r"(r[3]) : "r"(addr));
}
__device__ __forceinline__ void mma_bf16(float* c, const unsigned* a, const unsigned* b) {
    asm volatile(
        "mma.sync.aligned.m16n8k16.row.col.f32.bf16.bf16.f32 "
        "{%0,%1,%2,%3}, {%4,%5,%6,%7}, {%8,%9}, {%0,%1,%2,%3};"
        : "+f"(c[0]), "+f"(c[1]), "+f"(c[2]), "+f"(c[3])
        : "r"(a[0]), "r"(a[1]), "r"(a[2]), "r"(a[3]), "r"(b[0]), "r"(b[1]));
}
__device__ __forceinline__ void cp16(unsigned dst, const void* src, bool valid) {
    int sz = valid ? 16 : 0;
    asm volatile("cp.async.cg.shared.global [%0], [%1], 16, %2;"
                 :: "r"(dst), "l"(src), "r"(sz));
}
#define CP_COMMIT() asm volatile("cp.async.commit_group;")
#define CP_WAIT1()  asm volatile("cp.async.wait_group 1;")
#define CP_WAIT0()  asm volatile("cp.async.wait_group 0;")

template<int TN>
__global__ __launch_bounds__(256)
void gemm_tc_kernel(int a_sel, int K, long long w_off0, long long w_stride,
                    long long c_off0, long long c_stride, int Fout,
                    const float* __restrict__ att) {
    constexpr int TM = 128, BK = 16;
    constexpr int APITCH = 24;
    constexpr int BPITCH = TN + 8;
    constexpr int NF = TN / 32;
    constexpr int ASTAGE = TM * APITCH;
    constexpr int BSTAGE = BK * BPITCH;

    const __nv_bfloat16* Ahi = a_sel ? g_hhi : g_xhi;
    const __nv_bfloat16* Alo = a_sel ? g_hlo : g_xlo;
    long long w_off = w_off0 + (long long)blockIdx.y * w_stride;
    const __nv_bfloat16* Whi = g_whi + w_off;
    const __nv_bfloat16* Wlo = g_wlo + w_off;
    float* C = g_pool + c_off0 + (long long)blockIdx.y * c_stride;
    float* dots = blockIdx.y ? g_dr : g_dl;
    bool isL = (blockIdx.y == 0);
    __half* xh = a_sel ? g_xl2h : g_xl1h;

    extern __shared__ __align__(16) __nv_bfloat16 sm[];
    __nv_bfloat16* Ah = sm;
    __nv_bfloat16* Al = Ah + 3 * ASTAGE;
    __nv_bfloat16* Bh = Al + 3 * ASTAGE;
    __nv_bfloat16* Bl = Bh + 3 * BSTAGE;
    float* sdot = (float*)sm;          // reused after mainloop: [TM][4]

    int t = threadIdx.x;
    int lane = t & 31, wid = t >> 5;
    int warp_m = wid & 1, warp_n = wid >> 1;
    int m_off = warp_m * 64, n_off = warp_n * (TN / 4);
    int row0 = blockIdx.x * TM;
    int N = NN;

    float c[4][NF][4];
    #pragma unroll
    for (int i = 0; i < 4; i++)
        #pragma unroll
        for (int j = 0; j < NF; j++)
            #pragma unroll
            for (int q = 0; q < 4; q++) c[i][j][q] = 0.0f;

    int g = lane >> 3, r = lane & 7;
    int a_row = (g & 1) * 8 + r;
    int a_col = (g >> 1) * 8;
    int b_krow = lane & 15;
    int b_chalf = (lane >> 4) * 8;

    int am = t >> 1;
    int ac = (t & 1) * 8;

    const int NIT = K / BK;

    auto load_stage = [&](int it, int s) {
        int k0 = it * BK;
        int grow = row0 + am;
        bool v = grow < N;
        cp16((unsigned)__cvta_generic_to_shared(Ah + s * ASTAGE + am * APITCH + ac),
             Ahi + (size_t)grow * K + k0 + ac, v);
        cp16((unsigned)__cvta_generic_to_shared(Al + s * ASTAGE + am * APITCH + ac),
             Alo + (size_t)grow * K + k0 + ac, v);
        if (TN == 128) {
            int kk = t >> 4, ch = (t & 15) * 8;
            cp16((unsigned)__cvta_generic_to_shared(Bh + s * BSTAGE + kk * BPITCH + ch),
                 Whi + (size_t)(k0 + kk) * Fout + ch, true);
            cp16((unsigned)__cvta_generic_to_shared(Bl + s * BSTAGE + kk * BPITCH + ch),
                 Wlo + (size_t)(k0 + kk) * Fout + ch, true);
        } else {
            if (t < 128) {
                int kk = t >> 3, ch = (t & 7) * 8;
                cp16((unsigned)__cvta_generic_to_shared(Bh + s * BSTAGE + kk * BPITCH + ch),
                     Whi + (size_t)(k0 + kk) * Fout + ch, true);
                cp16((unsigned)__cvta_generic_to_shared(Bl + s * BSTAGE + kk * BPITCH + ch),
                     Wlo + (size_t)(k0 + kk) * Fout + ch, true);
            }
        }
    };

    load_stage(0, 0);
    CP_COMMIT();
    if (NIT > 1) load_stage(1, 1);
    CP_COMMIT();

    for (int it = 0; it < NIT; it++) {
        CP_WAIT1();
        __syncthreads();
        if (it + 2 < NIT) load_stage(it + 2, (it + 2) % 3);
        CP_COMMIT();

        int s = it % 3;
        unsigned ah[4][4], bh[NF][2];
        #pragma unroll
        for (int i = 0; i < 4; i++)
            ldsm_x4(ah[i], (unsigned)__cvta_generic_to_shared(
                        Ah + s * ASTAGE + (m_off + i * 16 + a_row) * APITCH + a_col));
        #pragma unroll
        for (int j = 0; j < NF; j += 2)
            ldsm_x4t(&bh[j][0], (unsigned)__cvta_generic_to_shared(
                        Bh + s * BSTAGE + b_krow * BPITCH + n_off + j * 8 + b_chalf));
        #pragma unroll
        for (int i = 0; i < 4; i++)
            #pragma unroll
            for (int j = 0; j < NF; j++) mma_bf16(c[i][j], ah[i], bh[j]);

        unsigned bl[NF][2];
        #pragma unroll
        for (int j = 0; j < NF; j += 2)
            ldsm_x4t(&bl[j][0], (unsigned)__cvta_generic_to_shared(
                        Bl + s * BSTAGE + b_krow * BPITCH + n_off + j * 8 + b_chalf));
        #pragma unroll
        for (int i = 0; i < 4; i++)
            #pragma unroll
            for (int j = 0; j < NF; j++) mma_bf16(c[i][j], ah[i], bl[j]);

        unsigned al[4][4];
        #pragma unroll
        for (int i = 0; i < 4; i++)
            ldsm_x4(al[i], (unsigned)__cvta_generic_to_shared(
                        Al + s * ASTAGE + (m_off + i * 16 + a_row) * APITCH + a_col));
        #pragma unroll
        for (int i = 0; i < 4; i++)
            #pragma unroll
            for (int j = 0; j < NF; j++) mma_bf16(c[i][j], al[i], bh[j]);
    }

    // ---- epilogue: stores (fp16 xl for L, fp32 for R) + fused att-dot ----
    CP_WAIT0();
    __syncthreads();                 // all ldsm reads done; smem reusable

    int lr = lane >> 2;
    int lc = (lane & 3) * 2;
    #pragma unroll
    for (int i = 0; i < 4; i++) {
        int gr = row0 + m_off + i * 16 + lr;
        float p0 = 0.0f, p1 = 0.0f;
        #pragma unroll
        for (int j = 0; j < NF; j++) {
            int gc = n_off + j * 8 + lc;
            float a0 = att[gc], a1 = att[gc + 1];
            if (gr < N) {
                if (isL)
                    *(__half2*)(xh + (size_t)gr * Fout + gc) =
                        __floats2half2_rn(c[i][j][0], c[i][j][1]);
                else
                    *(float2*)(C + (size_t)gr * Fout + gc) =
                        make_float2(c[i][j][0], c[i][j][1]);
            }
            if (gr + 8 < N) {
                if (isL)
                    *(__half2*)(xh + (size_t)(gr + 8) * Fout + gc) =
                        __floats2half2_rn(c[i][j][2], c[i][j][3]);
                else
                    *(float2*)(C + (size_t)(gr + 8) * Fout + gc) =
                        make_float2(c[i][j][2], c[i][j][3]);
            }
            p0 = fmaf(c[i][j][0], a0, fmaf(c[i][j][1], a1, p0));
            p1 = fmaf(c[i][j][2], a0, fmaf(c[i][j][3], a1, p1));
        }
        // butterfly over lane bits 0,1: lanes 4*lr..4*lr+3 hold same-row partials
        p0 += __shfl_xor_sync(0xFFFFFFFFu, p0, 1);
        p0 += __shfl_xor_sync(0xFFFFFFFFu, p0, 2);
        p1 += __shfl_xor_sync(0xFFFFFFFFu, p1, 1);
        p1 += __shfl_xor_sync(0xFFFFFFFFu, p1, 2);
        if ((lane & 3) == 0) {
            // atomic-free staging: each [row][warp_n] slot written exactly once
            sdot[(m_off + i * 16 + lr) * 4 + warp_n]     = p0;
            sdot[(m_off + i * 16 + lr + 8) * 4 + warp_n] = p1;
        }
    }
    __syncthreads();
    if (t < TM && row0 + t < N)
        dots[row0 + t] = sdot[t * 4] + sdot[t * 4 + 1]
                       + sdot[t * 4 + 2] + sdot[t * 4 + 3];
}

// ---------------------------------------------------------------------------
// Fused per-node kernel: warp/node, constant-shift softmax, batched 8-edge
// split-tree reduction. xl gather from fp16. Tail edges masked via -inf pinit
// (no per-edge predicates); per-lane ssum with one final cross-quad reduce.
// ---------------------------------------------------------------------------
template<int F, bool RELU, bool EMIT_BF16>
__global__ __launch_bounds__(256)
void node_kernel(long long xr_off,
                 const float* __restrict__ att,
                 const float* __restrict__ bias,
                 float* __restrict__ outp) {
    int node = (int)(((long long)blockIdx.x * blockDim.x + threadIdx.x) >> 5);
    int lane = threadIdx.x & 31;
    if (node >= NN) return;

    const __half* xlh = (F == 128) ? g_xl1h : g_xl2h;
    const float* xr = g_pool + xr_off;
    int s0 = g_off[node], s1 = g_off[node + 1];
    float dr = g_dr[node];
    bool h16 = (lane & 16) != 0;
    bool h8  = (lane & 8)  != 0;
    bool h4  = (lane & 4)  != 0;
    int psrc = lane >> 2;        // edge-within-batch this lane's s represents

    if (F == 128) {
        float4 xr4 = *(const float4*)(xr + (size_t)node * F + lane * 4);
        float4 at4 = *(const float4*)(att + lane * 4);
        float4 acc = make_float4(0.f, 0.f, 0.f, 0.f);
        float ssum = 0.0f;

        for (int base = s0; base < s1; base += 32) {
            int cnt = min(32, s1 - base);
            int safe = min(base + lane, s1 - 1);
            int sid = g_ssrc[safe];
            // tail lanes get -inf pinit -> w = 0, no per-edge predicates needed
            float pinit = (base + lane < s1)
                        ? 1.5f * (g_dl[sid] + dr) : -1e30f;

            for (int bq = 0; bq < cnt; bq += 8) {
                float4 av[8];
                float p[8];
                #pragma unroll
                for (int j = 0; j < 8; j++) {
                    int sj = __shfl_sync(0xFFFFFFFFu, sid, bq + j);
                    uint2 raw = *(const uint2*)(xlh + (size_t)sj * F + lane * 4);
                    float2 f01 = __half22float2(*(__half2*)&raw.x);
                    float2 f23 = __half22float2(*(__half2*)&raw.y);
                    av[j] = make_float4(f01.x, f01.y, f23.x, f23.y);
                    float zx = av[j].x + xr4.x, zy = av[j].y + xr4.y;
                    float zz = av[j].z + xr4.z, zw = av[j].w + xr4.w;
                    p[j] = fmaf(at4.x, fabsf(zx),
                           fmaf(at4.y, fabsf(zy),
                           fmaf(at4.z, fabsf(zz), at4.w * fabsf(zw))));
                }
                // split-tree reduce: 9 shfl for 8 edge sums
                float q[4];
                #pragma unroll
                for (int k = 0; k < 4; k++) {
                    float sendv = h16 ? p[k] : p[k + 4];
                    float recv = __shfl_xor_sync(0xFFFFFFFFu, sendv, 16);
                    q[k] = (h16 ? p[k + 4] : p[k]) + recv;
                }
                float rr[2];
                #pragma unroll
                for (int k = 0; k < 2; k++) {
                    float sendv = h8 ? q[k] : q[k + 2];
                    float recv = __shfl_xor_sync(0xFFFFFFFFu, sendv, 8);
                    rr[k] = (h8 ? q[k + 2] : q[k]) + recv;
                }
                float sendv = h4 ? rr[0] : rr[1];
                float recv = __shfl_xor_sync(0xFFFFFFFFu, sendv, 4);
                float s = (h4 ? rr[1] : rr[0]) + recv;
                s += __shfl_xor_sync(0xFFFFFFFFu, s, 2);
                s += __shfl_xor_sync(0xFFFFFFFFu, s, 1);
                // lanes 4j..4j+3 hold edge bq+j's abs-sum; add its pinit
                s += __shfl_sync(0xFFFFFFFFu, pinit, bq + psrc);
                float w = __expf(fmaf(0.4f, s, -20.0f));
                ssum += w;   // per-lane: own quad edge only; reduced at end
                #pragma unroll
                for (int j = 0; j < 8; j++) {
                    float wj = __shfl_sync(0xFFFFFFFFu, w, 4 * j);
                    acc.x = fmaf(wj, av[j].x, acc.x);
                    acc.y = fmaf(wj, av[j].y, acc.y);
                    acc.z = fmaf(wj, av[j].z, acc.z);
                    acc.w = fmaf(wj, av[j].w, acc.w);
                }
            }
        }
        // cross-quad ssum reduce (each bit0/bit1 column sums all 8 quads)
        ssum += __shfl_xor_sync(0xFFFFFFFFu, ssum, 4);
        ssum += __shfl_xor_sync(0xFFFFFFFFu, ssum, 8);
        ssum += __shfl_xor_sync(0xFFFFFFFFu, ssum, 16);

        float inv = 1.0f / (ssum + 1e-16f);
        float4 bb = *(const float4*)(bias + lane * 4);
        float v0 = acc.x * inv + bb.x, v1 = acc.y * inv + bb.y;
        float v2 = acc.z * inv + bb.z, v3 = acc.w * inv + bb.w;
        if (RELU) {
            v0 = fmaxf(v0, 0.f); v1 = fmaxf(v1, 0.f);
            v2 = fmaxf(v2, 0.f); v3 = fmaxf(v3, 0.f);
        }
        if (EMIT_BF16) {
            size_t o = (size_t)node * F + lane * 4;
            __nv_bfloat16 h0 = __float2bfloat16(v0), h1 = __float2bfloat16(v1);
            __nv_bfloat16 h2 = __float2bfloat16(v2), h3 = __float2bfloat16(v3);
            *(__nv_bfloat162*)(g_hhi + o)     = __nv_bfloat162(h0, h1);
            *(__nv_bfloat162*)(g_hhi + o + 2) = __nv_bfloat162(h2, h3);
            *(__nv_bfloat162*)(g_hlo + o) = __nv_bfloat162(
                __float2bfloat16(v0 - __bfloat162float(h0)),
                __float2bfloat16(v1 - __bfloat162float(h1)));
            *(__nv_bfloat162*)(g_hlo + o + 2) = __nv_bfloat162(
                __float2bfloat16(v2 - __bfloat162float(h2)),
                __float2bfloat16(v3 - __bfloat162float(h3)));
        } else {
            *(float4*)(outp + (size_t)node * F + lane * 4) = make_float4(v0, v1, v2, v3);
        }
    } else { // F == 64
        float2 xr2 = *(const float2*)(xr + (size_t)node * F + lane * 2);
        float2 at2 = *(const float2*)(att + lane * 2);
        float2 acc = make_float2(0.f, 0.f);
        float ssum = 0.0f;

        for (int base = s0; base < s1; base += 32) {
            int cnt = min(32, s1 - base);
            int safe = min(base + lane, s1 - 1);
            int sid = g_ssrc[safe];
            float pinit = (base + lane < s1)
                        ? 1.5f * (g_dl[sid] + dr) : -1e30f;

            for (int bq = 0; bq < cnt; bq += 8) {
                float2 av[8];
                float p[8];
                #pragma unroll
                for (int j = 0; j < 8; j++) {
                    int sj = __shfl_sync(0xFFFFFFFFu, sid, bq + j);
                    unsigned raw = *(const unsigned*)(xlh + (size_t)sj * F + lane * 2);
                    av[j] = __half22float2(*(__half2*)&raw);
                    float zx = av[j].x + xr2.x, zy = av[j].y + xr2.y;
                    p[j] = fmaf(at2.x, fabsf(zx), at2.y * fabsf(zy));
                }
                float q[4];
                #pragma unroll
                for (int k = 0; k < 4; k++) {
                    float sendv = h16 ? p[k] : p[k + 4];
                    float recv = __shfl_xor_sync(0xFFFFFFFFu, sendv, 16);
                    q[k] = (h16 ? p[k + 4] : p[k]) + recv;
                }
                float rr[2];
                #pragma unroll
                for (int k = 0; k < 2; k++) {
                    float sendv = h8 ? q[k] : q[k + 2];
                    float recv = __shfl_xor_sync(0xFFFFFFFFu, sendv, 8);
                    rr[k] = (h8 ? q[k + 2] : q[k]) + recv;
                }
                float sendv = h4 ? rr[0] : rr[1];
                float recv = __shfl_xor_sync(0xFFFFFFFFu, sendv, 4);
                float s = (h4 ? rr[1] : rr[0]) + recv;
                s += __shfl_xor_sync(0xFFFFFFFFu, s, 2);
                s += __shfl_xor_sync(0xFFFFFFFFu, s, 1);
                s += __shfl_sync(0xFFFFFFFFu, pinit, bq + psrc);
                float w = __expf(fmaf(0.4f, s, -20.0f));
                ssum += w;
                #pragma unroll
                for (int j = 0; j < 8; j++) {
                    float wj = __shfl_sync(0xFFFFFFFFu, w, 4 * j);
                    acc.x = fmaf(wj, av[j].x, acc.x);
                    acc.y = fmaf(wj, av[j].y, acc.y);
                }
            }
        }
        ssum += __shfl_xor_sync(0xFFFFFFFFu, ssum, 4);
        ssum += __shfl_xor_sync(0xFFFFFFFFu, ssum, 8);
        ssum += __shfl_xor_sync(0xFFFFFFFFu, ssum, 16);

        float inv = 1.0f / (ssum + 1e-16f);
        float2 bb = *(const float2*)(bias + lane * 2);
        float v0 = acc.x * inv + bb.x, v1 = acc.y * inv + bb.y;
        if (RELU) { v0 = fmaxf(v0, 0.f); v1 = fmaxf(v1, 0.f); }
        *(float2*)(outp + (size_t)node * F + lane * 2) = make_float2(v0, v1);
    }
}

// ---------------------------------------------------------------------------
// Host launch (serial main stream + CSR/convert side streams)
// ---------------------------------------------------------------------------
extern "C" void kernel_launch(void* const* d_in, const int* in_sizes, int n_in,
                              void* d_out, int out_size) {
    const float* x    = (const float*)d_in[0];
    const int*   ei   = (const int*)d_in[1];
    const float* Wl1  = (const float*)d_in[2];
    const float* Wr1  = (const float*)d_in[3];
    const float* att1 = (const float*)d_in[4];
    const float* b1   = (const float*)d_in[5];
    const float* Wl2  = (const float*)d_in[6];
    const float* Wr2  = (const float*)d_in[7];
    const float* att2 = (const float*)d_in[8];
    const float* b2   = (const float*)d_in[9];
    float* out = (float*)d_out;

    int E = in_sizes[1] / 2;
    const int* srcp = ei;
    const int* dstp = ei + E;

    constexpr int SMEM128 = (3 * 128 * 24 * 2 + 3 * 16 * (128 + 8) * 2) * 2;  // 62976 B
    constexpr int SMEM64  = (3 * 128 * 24 * 2 + 3 * 16 * (64 + 8) * 2) * 2;   // 50688 B

    static cudaStream_t s2 = nullptr, s3 = nullptr;
    static cudaEvent_t e_fork, e_w1, e_w2, e_csr;
    if (!s2) {
        cudaStreamCreateWithFlags(&s2, cudaStreamNonBlocking);
        cudaStreamCreateWithFlags(&s3, cudaStreamNonBlocking);
        cudaEventCreateWithFlags(&e_fork, cudaEventDisableTiming);
        cudaEventCreateWithFlags(&e_w1,   cudaEventDisableTiming);
        cudaEventCreateWithFlags(&e_w2,   cudaEventDisableTiming);
        cudaEventCreateWithFlags(&e_csr,  cudaEventDisableTiming);
        cudaFuncSetAttribute((const void*)gemm_tc_kernel<128>,
                             cudaFuncAttributeMaxDynamicSharedMemorySize, SMEM128);
        cudaFuncSetAttribute((const void*)gemm_tc_kernel<64>,
                             cudaFuncAttributeMaxDynamicSharedMemorySize, SMEM64);
    }

    cudaStream_t m = 0;
    int eBlocks4 = (E + 1023) / 1024;
    int warpGrid = (NN * 32 + 255) / 256;

    cudaEventRecord(e_fork, m);
    cudaStreamWaitEvent(s2, e_fork, 0);
    cudaStreamWaitEvent(s3, e_fork, 0);

    // m: x convert
    cvt_kernel<<<(int)(((long long)NN * FIN / 4 + 255) / 256), 256, 0, m>>>(
        x, 0, 0, (long long)NN * FIN);

    // s3: weight converts
    cvt_kernel<<<32, 256, 0, s3>>>(Wl1, 1, 0, 32768);
    cvt_kernel<<<32, 256, 0, s3>>>(Wr1, 1, 32768, 32768);
    cudaEventRecord(e_w1, s3);
    cvt_kernel<<<8,  256, 0, s3>>>(Wl2, 1, 65536, 8192);
    cvt_kernel<<<8,  256, 0, s3>>>(Wr2, 1, 73728, 8192);
    cudaEventRecord(e_w2, s3);

    // m: merged layer-1 GEMM (L y=0 -> fp16 xl1 + g_dl, R y=1 -> fp32 xr1 + g_dr)
    cudaStreamWaitEvent(m, e_w1, 0);
    gemm_tc_kernel<128><<<dim3((NN + 127) / 128, 2), 256, SMEM128, m>>>(
        0, FIN, 0, 32768, OFF_XL1, (long long)NN * HH, HH, att1);

    // s2: CSR build (overlaps converts + gemm1)
    zero_cnt_kernel<<<NBLK, 256, 0, s2>>>();
    hist_kernel<<<eBlocks4, 256, 0, s2>>>(dstp, E);
    scan1_kernel<<<NBLK, 256, 0, s2>>>();
    scan2_kernel<<<1, 256, 0, s2>>>();
    scan3_kernel<<<NBLK, 256, 0, s2>>>(E);
    scatter_kernel<<<eBlocks4, 256, 0, s2>>>(srcp, dstp, E);
    cudaEventRecord(e_csr, s2);

    // m: node1 (fp16 gather; emits h as bf16 hi/lo)
    cudaStreamWaitEvent(m, e_csr, 0);
    node_kernel<128, true, true><<<warpGrid, 256, 0, m>>>(
        OFF_XR1, att1, b1, nullptr);

    // m: merged layer-2 GEMM
    cudaStreamWaitEvent(m, e_w2, 0);
    gemm_tc_kernel<64><<<dim3((NN + 127) / 128, 2), 256, SMEM64, m>>>(
        1, HH, 65536, 8192, OFF_XL2, (long long)NN * CC, CC, att2);

    // m: node2 -> out (fp16 gather)
    node_kernel<64, false, false><<<warpGrid, 256, 0, m>>>(
        OFF_XR2, att2, b2, out);
}